// round 8
// baseline (speedup 1.0000x reference)
#include <cuda_runtime.h>
#include <cuda_bf16.h>
#include <math.h>
#include <cstdint>

#define S_LEN 2048
#define HID   2048
#define NH    16
#define NKV   4
#define HD    128
#define BATCH 2
#define MROWS (BATCH * S_LEN)          // 4096

// ---------------- fp32 scratch ----------------
__device__ float g_q[(size_t)BATCH * NH  * S_LEN * HD];   // [b][h][s][d]
__device__ float g_k[(size_t)BATCH * NKV * S_LEN * HD];
__device__ float g_v[(size_t)BATCH * NKV * S_LEN * HD];
__device__ float g_ao[(size_t)MROWS * HID];               // [b][s][h*128+d]

// ---------------- presplit bf16 hi/lo scratch ----------------
__device__ __nv_bfloat16 g_xh[(size_t)MROWS * HID],  g_xl[(size_t)MROWS * HID];
__device__ __nv_bfloat16 g_wqh[(size_t)2048 * HID],  g_wql[(size_t)2048 * HID];
__device__ __nv_bfloat16 g_wkh[(size_t)512  * HID],  g_wkl[(size_t)512  * HID];
__device__ __nv_bfloat16 g_wvh[(size_t)512  * HID],  g_wvl[(size_t)512  * HID];
__device__ __nv_bfloat16 g_woh[(size_t)2048 * HID],  g_wol[(size_t)2048 * HID];
__device__ __nv_bfloat16 g_aoh[(size_t)MROWS * HID], g_aol[(size_t)MROWS * HID];

// ===========================================================================
// Helpers
// ===========================================================================
__device__ __forceinline__ uint32_t smem_u32(const void* p) {
    uint32_t a;
    asm("{ .reg .u64 t; cvta.to.shared.u64 t, %1; cvt.u32.u64 %0, t; }"
        : "=r"(a) : "l"(p));
    return a;
}
__device__ __forceinline__ void ldsm_x4(uint32_t r[4], uint32_t a) {
    asm volatile("ldmatrix.sync.aligned.m8n8.x4.shared.b16 {%0,%1,%2,%3}, [%4];"
                 : "=r"(r[0]), "=r"(r[1]), "=r"(r[2]), "=r"(r[3]) : "r"(a));
}
__device__ __forceinline__ void ldsm_x4_t(uint32_t r[4], uint32_t a) {
    asm volatile("ldmatrix.sync.aligned.m8n8.x4.trans.shared.b16 {%0,%1,%2,%3}, [%4];"
                 : "=r"(r[0]), "=r"(r[1]), "=r"(r[2]), "=r"(r[3]) : "r"(a));
}
__device__ __forceinline__ void mma16816(float c[4], const uint32_t a[4],
                                         uint32_t b0, uint32_t b1) {
    asm volatile("mma.sync.aligned.m16n8k16.row.col.f32.bf16.bf16.f32 "
                 "{%0,%1,%2,%3}, {%4,%5,%6,%7}, {%8,%9}, {%0,%1,%2,%3};"
                 : "+f"(c[0]), "+f"(c[1]), "+f"(c[2]), "+f"(c[3])
                 : "r"(a[0]), "r"(a[1]), "r"(a[2]), "r"(a[3]), "r"(b0), "r"(b1));
}
__device__ __forceinline__ void split2(float x0, float x1, uint32_t& hi, uint32_t& lo) {
    asm("cvt.rn.bf16x2.f32 %0, %1, %2;" : "=r"(hi) : "f"(x1), "f"(x0));
    float h0 = __uint_as_float(hi << 16);
    float h1 = __uint_as_float(hi & 0xFFFF0000u);
    float l0 = x0 - h0;
    float l1 = x1 - h1;
    asm("cvt.rn.bf16x2.f32 %0, %1, %2;" : "=r"(lo) : "f"(l1), "f"(l0));
}
__device__ __forceinline__ void cp_async16(uint32_t dst, const void* src) {
    asm volatile("cp.async.cg.shared.global [%0], [%1], 16;" :: "r"(dst), "l"(src));
}
#define CP_COMMIT() asm volatile("cp.async.commit_group;" ::: "memory")
#define CP_WAIT(n)  asm volatile("cp.async.wait_group %0;" :: "n"(n) : "memory")

#define SWZ(o) ((o) ^ (((o) >> 3) & 0x70))

// ===========================================================================
// Split pass: fp32 -> bf16 hi/lo
// ===========================================================================
__global__ void split_f32(const float4* __restrict__ src,
                          uint2* __restrict__ hi, uint2* __restrict__ lo, int n4)
{
    int i = blockIdx.x * blockDim.x + threadIdx.x;
    if (i < n4) {
        float4 v = src[i];
        uint32_t h0, l0, h1, l1;
        split2(v.x, v.y, h0, l0);
        split2(v.z, v.w, h1, l1);
        hi[i] = make_uint2(h0, h1);
        lo[i] = make_uint2(l0, l1);
    }
}

// ===========================================================================
// Split-bf16 GEMM: 256 threads / 8 warps (4M x 2N), warp tile 32x64.
// Presplit inputs, 3-stage cp.async pipeline, zero in-loop conversion.
// Stage = A(128 rows x [hi32|lo32] bf16 = 16KB) + B(16KB) = 32KB. 3 stages.
// ===========================================================================
#define KCHUNKS 64
#define GSTAGE  32768
#define GEMM_SMEM (3 * GSTAGE)

__device__ __forceinline__ void gemm_tile_256(
    const __nv_bfloat16* __restrict__ Ah, const __nv_bfloat16* __restrict__ Al,
    const __nv_bfloat16* __restrict__ Bh, const __nv_bfloat16* __restrict__ Bl,
    int m0, int n0, float cacc[2][8][4], char* smem)
{
    int tid = threadIdx.x;
    int warp = tid >> 5, lane = tid & 31;
    int wm = warp & 3, wn = warp >> 2;          // 4 M-slices x 2 N-slices
    int lr16 = lane & 15, lhalf = (lane >> 4) * 16;
    uint32_t sbase = smem_u32(smem);

    // cp.async mapping: 256 threads x 4 x 16B per operand tile (16KB each)
    int ar = tid >> 1;                 // row 0..127
    int hl = tid & 1;                  // 0: hi plane (bytes 0-63), 1: lo plane
    const __nv_bfloat16* asrc = (hl ? Al : Ah) + (size_t)(m0 + ar) * HID;
    const __nv_bfloat16* bsrc = (hl ? Bl : Bh) + (size_t)(n0 + ar) * HID;
    uint32_t doff[4];
#pragma unroll
    for (int j = 0; j < 4; j++)
        doff[j] = SWZ((uint32_t)ar * 128 + hl * 64 + j * 16);

#pragma unroll
    for (int mt = 0; mt < 2; mt++)
#pragma unroll
        for (int ng = 0; ng < 8; ng++)
#pragma unroll
            for (int i = 0; i < 4; i++) cacc[mt][ng][i] = 0.f;

    auto load_stage = [&](int s, int c) {
        uint32_t st = sbase + s * GSTAGE;
        const __nv_bfloat16* a = asrc + c * 32;
        const __nv_bfloat16* b = bsrc + c * 32;
#pragma unroll
        for (int j = 0; j < 4; j++) {
            cp_async16(st + doff[j], a + j * 8);
            cp_async16(st + 16384 + doff[j], b + j * 8);
        }
        CP_COMMIT();
    };

    load_stage(0, 0);
    load_stage(1, 1);
    load_stage(2, 2);

    for (int c = 0; c < KCHUNKS; c++) {
        if (c + 2 < KCHUNKS)      CP_WAIT(2);
        else if (c + 1 < KCHUNKS) CP_WAIT(1);
        else                      CP_WAIT(0);
        __syncthreads();

        int s = c % 3;
        uint32_t abase = sbase + s * GSTAGE;
        uint32_t bbase = abase + 16384;

#pragma unroll
        for (int seg = 0; seg < 3; seg++) {
            int sa = (seg == 1) ? 64 : 0;   // A: hi, lo, hi
            int sb = (seg == 2) ? 64 : 0;   // B: hi, hi, lo
#pragma unroll
            for (int kk = 0; kk < 2; kk++) {
                uint32_t af[2][4];
#pragma unroll
                for (int mt = 0; mt < 2; mt++) {
                    uint32_t off = (uint32_t)(wm * 32 + mt * 16 + lr16) * 128
                                   + sa + kk * 32 + lhalf;
                    ldsm_x4(af[mt], abase + SWZ(off));
                }
                uint32_t b0[8], b1[8];
#pragma unroll
                for (int t = 0; t < 4; t++) {
                    uint32_t off = (uint32_t)(wn * 64 + t * 16 + lr16) * 128
                                   + sb + kk * 32 + lhalf;
                    uint32_t r[4];
                    ldsm_x4(r, bbase + SWZ(off));
                    b0[2 * t] = r[0]; b0[2 * t + 1] = r[1];
                    b1[2 * t] = r[2]; b1[2 * t + 1] = r[3];
                }
#pragma unroll
                for (int mt = 0; mt < 2; mt++)
#pragma unroll
                    for (int ng = 0; ng < 8; ng++)
                        mma16816(cacc[mt][ng], af[mt], b0[ng], b1[ng]);
            }
        }
        __syncthreads();
        if (c + 3 < KCHUNKS) load_stage(s, c + 3);
    }
}

__global__ void __launch_bounds__(256) gemm_qkv_mma()
{
    extern __shared__ char smem[];
    int nt = blockIdx.x;
    int m0 = blockIdx.y * 128;

    const __nv_bfloat16 *Bh, *Bl; float* dst_base; int h, nkvh;
    if (nt < 16)      { Bh = g_wqh; Bl = g_wql; h = nt;      dst_base = g_q; nkvh = NH;  }
    else if (nt < 20) { Bh = g_wkh; Bl = g_wkl; h = nt - 16; dst_base = g_k; nkvh = NKV; }
    else              { Bh = g_wvh; Bl = g_wvl; h = nt - 20; dst_base = g_v; nkvh = NKV; }

    float cacc[2][8][4];
    gemm_tile_256(g_xh, g_xl, Bh, Bl, m0, h * HD, cacc, smem);

    int tid = threadIdx.x;
    int warp = tid >> 5, lane = tid & 31;
    int wm = warp & 3, wn = warp >> 2;
    int r0 = lane >> 2, c0 = (lane & 3) * 2;

#pragma unroll
    for (int mt = 0; mt < 2; mt++) {
#pragma unroll
        for (int ng = 0; ng < 8; ng++) {
            int col = wn * 64 + ng * 8 + c0;
#pragma unroll
            for (int half = 0; half < 2; half++) {
                int mg = m0 + wm * 32 + mt * 16 + r0 + half * 8;
                int b = mg >> 11, s = mg & (S_LEN - 1);
                float* d = dst_base + ((size_t)(b * nkvh + h) * S_LEN + s) * HD + col;
                *(float2*)d = make_float2(cacc[mt][ng][2 * half],
                                          cacc[mt][ng][2 * half + 1]);
            }
        }
    }
}

__global__ void __launch_bounds__(256) gemm_wo_mma(float* __restrict__ out)
{
    extern __shared__ char smem[];
    int n0 = blockIdx.x * 128;
    int m0 = blockIdx.y * 128;

    float cacc[2][8][4];
    gemm_tile_256(g_aoh, g_aol, g_woh, g_wol, m0, n0, cacc, smem);

    int tid = threadIdx.x;
    int warp = tid >> 5, lane = tid & 31;
    int wm = warp & 3, wn = warp >> 2;
    int r0 = lane >> 2, c0 = (lane & 3) * 2;

#pragma unroll
    for (int mt = 0; mt < 2; mt++) {
#pragma unroll
        for (int ng = 0; ng < 8; ng++) {
            int col = n0 + wn * 64 + ng * 8 + c0;
#pragma unroll
            for (int half = 0; half < 2; half++) {
                int mg = m0 + wm * 32 + mt * 16 + r0 + half * 8;
                *(float2*)&out[(size_t)mg * HID + col] =
                    make_float2(cacc[mt][ng][2 * half], cacc[mt][ng][2 * half + 1]);
            }
        }
    }
}

// ---------------------------------------------------------------------------
// RoPE (in place, fp32). 256 threads = 4 rows per block.
// ---------------------------------------------------------------------------
__device__ __forceinline__ void rope_rows(float* g, int nrows_log2_mask)
{
    int r = blockIdx.x * 4 + (threadIdx.x >> 6);
    int d = threadIdx.x & 63;
    float* base = g + (size_t)r * HD;
    int s = r & (S_LEN - 1);
    float inv = (float)exp2(-(double)d * 0.20762050593046747);
    float ang = (float)s * inv;
    float sn, cs;
    sincosf(ang, &sn, &cs);
    float x1 = base[d], x2 = base[d + 64];
    base[d]      = x1 * cs - x2 * sn;
    base[d + 64] = x1 * sn + x2 * cs;
}
__global__ void rope_q() { rope_rows(g_q, 0); }
__global__ void rope_k() { rope_rows(g_k, 0); }

// ===========================================================================
// HMMA flash attention (R5 verbatim — known 605us)
// BM=128 (8 warps x m16), BN=64 keys/tile. 256 threads.
// ===========================================================================
#define AT_QH 0
#define AT_QL 32768
#define AT_KH 65536
#define AT_KL 81920
#define AT_VH 98304
#define AT_VL 114688
#define ATTN_SMEM 131072

__global__ void __launch_bounds__(256, 1) attn_mma(const float* __restrict__ kw)
{
    extern __shared__ char smem[];
    uint32_t sb = smem_u32(smem);

    int tid = threadIdx.x;
    int wq = tid >> 5, lane = tid & 31;
    int lr16 = lane & 15;
    int lhalf = (lane >> 4) * 16;

    int mt = blockIdx.x, h = blockIdx.y, b = blockIdx.z;
    int m0 = mt * 128;
    int kh = h >> 2;
    float scale = kw[h] * 0.08838834764831845f;

    const float* qg = g_q + ((size_t)(b * NH  + h ) * S_LEN + m0) * HD;
    const float* kg = g_k + ((size_t)(b * NKV + kh) * S_LEN) * HD;
    const float* vg = g_v + ((size_t)(b * NKV + kh) * S_LEN) * HD;

    {
        int row = tid >> 1;
        int dst = (tid & 1) * 64;
        const float* src = qg + (size_t)row * HD + dst;
        char* qh = smem + AT_QH + (dst >> 6) * 16384;
        char* ql = smem + AT_QL + (dst >> 6) * 16384;
#pragma unroll
        for (int j = 0; j < 16; j++) {
            float4 v = *(const float4*)(src + j * 4);
            v.x *= scale; v.y *= scale; v.z *= scale; v.w *= scale;
            uint32_t h0, l0, h1, l1;
            split2(v.x, v.y, h0, l0);
            split2(v.z, v.w, h1, l1);
            uint32_t off = (uint32_t)row * 128 + ((dst + j * 4) & 63) * 2;
            *(uint2*)(qh + SWZ(off)) = make_uint2(h0, h1);
            *(uint2*)(ql + SWZ(off)) = make_uint2(l0, l1);
        }
    }

    float m1 = -1e30f, m2 = -1e30f, l1s = 0.f, l2s = 0.f;
    float oacc[16][4];
#pragma unroll
    for (int ng = 0; ng < 16; ng++)
#pragma unroll
        for (int i = 0; i < 4; i++) oacc[ng][i] = 0.f;

    int vrow_off = (lane & 7) + ((lane >> 3) & 1) * 8;
    int vcol8 = (lane >> 4) * 8;

    int ntiles = 2 * mt + 2;
    for (int nt = 0; nt < ntiles; nt++) {
        int n0 = nt * 64;
        __syncthreads();

        {
            int row = tid >> 2;
            int dst = (tid & 3) * 32;
            int half = dst >> 6;
            const float* ks = kg + (size_t)(n0 + row) * HD + dst;
            const float* vs = vg + (size_t)(n0 + row) * HD + dst;
            char* kh_t = smem + AT_KH + half * 8192;
            char* kl_t = smem + AT_KL + half * 8192;
            char* vh_t = smem + AT_VH + half * 8192;
            char* vl_t = smem + AT_VL + half * 8192;
#pragma unroll
            for (int j = 0; j < 8; j++) {
                uint32_t off = SWZ((uint32_t)row * 128 + ((dst + j * 4) & 63) * 2);
                float4 v = *(const float4*)(ks + j * 4);
                uint32_t h0, l0, h1, l1;
                split2(v.x, v.y, h0, l0);
                split2(v.z, v.w, h1, l1);
                *(uint2*)(kh_t + off) = make_uint2(h0, h1);
                *(uint2*)(kl_t + off) = make_uint2(l0, l1);
                v = *(const float4*)(vs + j * 4);
                split2(v.x, v.y, h0, l0);
                split2(v.z, v.w, h1, l1);
                *(uint2*)(vh_t + off) = make_uint2(h0, h1);
                *(uint2*)(vl_t + off) = make_uint2(l0, l1);
            }
        }
        __syncthreads();

        float sacc[8][4];
#pragma unroll
        for (int ng = 0; ng < 8; ng++)
#pragma unroll
            for (int i = 0; i < 4; i++) sacc[ng][i] = 0.f;

#pragma unroll
        for (int seg = 0; seg < 3; seg++) {
            uint32_t qbase = sb + ((seg == 1) ? AT_QL : AT_QH);
            uint32_t kbase = sb + ((seg == 2) ? AT_KL : AT_KH);
#pragma unroll
            for (int ks = 0; ks < 8; ks++) {
                int half = ks >> 2;
                uint32_t koff = (ks & 3) * 32 + lhalf;
                uint32_t af[4];
                ldsm_x4(af, qbase + half * 16384
                            + SWZ((uint32_t)(wq * 16 + lr16) * 128 + koff));
                uint32_t b0[8], b1[8];
#pragma unroll
                for (int t = 0; t < 4; t++) {
                    uint32_t r[4];
                    ldsm_x4(r, kbase + half * 8192
                               + SWZ((uint32_t)(t * 16 + lr16) * 128 + koff));
                    b0[2 * t] = r[0]; b0[2 * t + 1] = r[1];
                    b1[2 * t] = r[2]; b1[2 * t + 1] = r[3];
                }
#pragma unroll
                for (int ng = 0; ng < 8; ng++)
                    mma16816(sacc[ng], af, b0[ng], b1[ng]);
            }
        }

        if (nt >= 2 * mt) {
            int rg1 = m0 + wq * 16 + (lane >> 2);
            int rg2 = rg1 + 8;
            int cb = n0 + (lane & 3) * 2;
#pragma unroll
            for (int ng = 0; ng < 8; ng++) {
                int c0g = cb + ng * 8;
                if (c0g > rg1)     sacc[ng][0] = -1e30f;
                if (c0g + 1 > rg1) sacc[ng][1] = -1e30f;
                if (c0g > rg2)     sacc[ng][2] = -1e30f;
                if (c0g + 1 > rg2) sacc[ng][3] = -1e30f;
            }
        }

        float rmax1 = -1e30f, rmax2 = -1e30f;
#pragma unroll
        for (int ng = 0; ng < 8; ng++) {
            rmax1 = fmaxf(rmax1, fmaxf(sacc[ng][0], sacc[ng][1]));
            rmax2 = fmaxf(rmax2, fmaxf(sacc[ng][2], sacc[ng][3]));
        }
        rmax1 = fmaxf(rmax1, __shfl_xor_sync(0xffffffffu, rmax1, 1));
        rmax1 = fmaxf(rmax1, __shfl_xor_sync(0xffffffffu, rmax1, 2));
        rmax2 = fmaxf(rmax2, __shfl_xor_sync(0xffffffffu, rmax2, 1));
        rmax2 = fmaxf(rmax2, __shfl_xor_sync(0xffffffffu, rmax2, 2));

        float mn1 = fmaxf(m1, rmax1);
        float mn2 = fmaxf(m2, rmax2);
        float alpha1 = __expf(m1 - mn1);
        float alpha2 = __expf(m2 - mn2);
        m1 = mn1; m2 = mn2;

        float rsum1 = 0.f, rsum2 = 0.f;
#pragma unroll
        for (int ng = 0; ng < 8; ng++) {
            sacc[ng][0] = __expf(sacc[ng][0] - mn1);
            sacc[ng][1] = __expf(sacc[ng][1] - mn1);
            sacc[ng][2] = __expf(sacc[ng][2] - mn2);
            sacc[ng][3] = __expf(sacc[ng][3] - mn2);
            rsum1 += sacc[ng][0] + sacc[ng][1];
            rsum2 += sacc[ng][2] + sacc[ng][3];
        }
        rsum1 += __shfl_xor_sync(0xffffffffu, rsum1, 1);
        rsum1 += __shfl_xor_sync(0xffffffffu, rsum1, 2);
        rsum2 += __shfl_xor_sync(0xffffffffu, rsum2, 1);
        rsum2 += __shfl_xor_sync(0xffffffffu, rsum2, 2);
        l1s = l1s * alpha1 + rsum1;
        l2s = l2s * alpha2 + rsum2;

#pragma unroll
        for (int ng = 0; ng < 16; ng++) {
            oacc[ng][0] *= alpha1; oacc[ng][1] *= alpha1;
            oacc[ng][2] *= alpha2; oacc[ng][3] *= alpha2;
        }

#pragma unroll
        for (int ks = 0; ks < 4; ks++) {
            uint32_t pha[4], pla[4];
            split2(sacc[2 * ks][0],     sacc[2 * ks][1],     pha[0], pla[0]);
            split2(sacc[2 * ks][2],     sacc[2 * ks][3],     pha[1], pla[1]);
            split2(sacc[2 * ks + 1][0], sacc[2 * ks + 1][1], pha[2], pla[2]);
            split2(sacc[2 * ks + 1][2], sacc[2 * ks + 1][3], pha[3], pla[3]);

            uint32_t vrow = (uint32_t)(ks * 16 + vrow_off) * 128;
#pragma unroll
            for (int t = 0; t < 8; t++) {
                int half = t >> 2;
                uint32_t coff = ((t & 3) * 16 + vcol8) * 2;
                uint32_t r[4];
                ldsm_x4_t(r, sb + AT_VH + half * 8192 + SWZ(vrow + coff));
                mma16816(oacc[2 * t],     pha, r[0], r[1]);
                mma16816(oacc[2 * t + 1], pha, r[2], r[3]);
                mma16816(oacc[2 * t],     pla, r[0], r[1]);
                mma16816(oacc[2 * t + 1], pla, r[2], r[3]);
            }
#pragma unroll
            for (int t = 0; t < 8; t++) {
                int half = t >> 2;
                uint32_t coff = ((t & 3) * 16 + vcol8) * 2;
                uint32_t r[4];
                ldsm_x4_t(r, sb + AT_VL + half * 8192 + SWZ(vrow + coff));
                mma16816(oacc[2 * t],     pha, r[0], r[1]);
                mma16816(oacc[2 * t + 1], pha, r[2], r[3]);
            }
        }
    }

    float inv1 = 1.0f / l1s;
    float inv2 = 1.0f / l2s;
    int r1 = m0 + wq * 16 + (lane >> 2);
    int c0 = (lane & 3) * 2;
    float* dst1 = g_ao + ((size_t)(b * S_LEN + r1)) * HID + h * HD;
    float* dst2 = g_ao + ((size_t)(b * S_LEN + r1 + 8)) * HID + h * HD;
#pragma unroll
    for (int ng = 0; ng < 16; ng++) {
        int d = ng * 8 + c0;
        *(float2*)(dst1 + d) = make_float2(oacc[ng][0] * inv1, oacc[ng][1] * inv1);
        *(float2*)(dst2 + d) = make_float2(oacc[ng][2] * inv2, oacc[ng][3] * inv2);
    }
}

// ---------------------------------------------------------------------------
// Launch
// ---------------------------------------------------------------------------
extern "C" void kernel_launch(void* const* d_in, const int* in_sizes, int n_in,
                              void* d_out, int out_size)
{
    const float* x  = (const float*)d_in[0];
    const float* wq = (const float*)d_in[1];
    const float* wk = (const float*)d_in[2];
    const float* wv = (const float*)d_in[3];
    const float* wo = (const float*)d_in[4];
    const float* kw = (const float*)d_in[5];
    float* out = (float*)d_out;

    cudaFuncSetAttribute(attn_mma, cudaFuncAttributeMaxDynamicSharedMemorySize,
                         ATTN_SMEM);
    cudaFuncSetAttribute(gemm_qkv_mma, cudaFuncAttributeMaxDynamicSharedMemorySize,
                         GEMM_SMEM);
    cudaFuncSetAttribute(gemm_wo_mma, cudaFuncAttributeMaxDynamicSharedMemorySize,
                         GEMM_SMEM);

    void *xh, *xl, *wqh, *wql, *wkh, *wkl, *wvh, *wvl, *woh, *wol, *ao, *aoh, *aol;
    cudaGetSymbolAddress(&xh, g_xh);   cudaGetSymbolAddress(&xl, g_xl);
    cudaGetSymbolAddress(&wqh, g_wqh); cudaGetSymbolAddress(&wql, g_wql);
    cudaGetSymbolAddress(&wkh, g_wkh); cudaGetSymbolAddress(&wkl, g_wkl);
    cudaGetSymbolAddress(&wvh, g_wvh); cudaGetSymbolAddress(&wvl, g_wvl);
    cudaGetSymbolAddress(&woh, g_woh); cudaGetSymbolAddress(&wol, g_wol);
    cudaGetSymbolAddress(&ao, g_ao);
    cudaGetSymbolAddress(&aoh, g_aoh); cudaGetSymbolAddress(&aol, g_aol);

    auto split = [&](const float* src, void* hi, void* lo, size_t n) {
        int n4 = (int)(n / 4);
        split_f32<<<(n4 + 255) / 256, 256>>>((const float4*)src,
                                             (uint2*)hi, (uint2*)lo, n4);
    };

    // presplit inputs
    split(x,  xh,  xl,  (size_t)MROWS * HID);
    split(wq, wqh, wql, (size_t)2048 * HID);
    split(wk, wkh, wkl, (size_t)512 * HID);
    split(wv, wvh, wvl, (size_t)512 * HID);
    split(wo, woh, wol, (size_t)2048 * HID);

    // QKV projection (256 threads, 8 warps, 32x64 warp tile)
    gemm_qkv_mma<<<dim3(24, 32), 256, GEMM_SMEM>>>();

    // RoPE (fp32, in place; 4 rows per block)
    rope_q<<<BATCH * NH * S_LEN / 4, 256>>>();
    rope_k<<<BATCH * NKV * S_LEN / 4, 256>>>();

    // Attention (R5, BM=128, 256 threads)
    attn_mma<<<dim3(S_LEN / 128, NH, BATCH), 256, ATTN_SMEM>>>(kw);

    // presplit attention output for the WO GEMM
    split((const float*)ao, aoh, aol, (size_t)MROWS * HID);

    // Output projection
    gemm_wo_mma<<<dim3(16, 32), 256, GEMM_SMEM>>>(out);
}

// round 9
// speedup vs baseline: 1.3903x; 1.3903x over previous
#include <cuda_runtime.h>
#include <cuda_bf16.h>
#include <cuda_fp16.h>
#include <math.h>
#include <cstdint>

#define S_LEN 2048
#define HID   2048
#define NH    16
#define NKV   4
#define HD    128
#define BATCH 2
#define MROWS (BATCH * S_LEN)          // 4096

// ---------------- fp32 scratch ----------------
__device__ float g_q[(size_t)BATCH * NH  * S_LEN * HD];   // [b][h][s][d]
__device__ float g_k[(size_t)BATCH * NKV * S_LEN * HD];
__device__ float g_v[(size_t)BATCH * NKV * S_LEN * HD];
__device__ float g_ao[(size_t)MROWS * HID];               // [b][s][h*128+d]

// ---------------- presplit fp16 scratch ----------------
__device__ __half g_xh[(size_t)MROWS * HID],  g_xl[(size_t)MROWS * HID];
__device__ __half g_aoh[(size_t)MROWS * HID], g_aol[(size_t)MROWS * HID];
__device__ __half g_wqs[(size_t)2048 * HID];
__device__ __half g_wks[(size_t)512  * HID];
__device__ __half g_wvs[(size_t)512  * HID];
__device__ __half g_wos[(size_t)2048 * HID];

// ===========================================================================
// Helpers
// ===========================================================================
__device__ __forceinline__ uint32_t smem_u32(const void* p) {
    uint32_t a;
    asm("{ .reg .u64 t; cvta.to.shared.u64 t, %1; cvt.u32.u64 %0, t; }"
        : "=r"(a) : "l"(p));
    return a;
}
__device__ __forceinline__ void ldsm_x4(uint32_t r[4], uint32_t a) {
    asm volatile("ldmatrix.sync.aligned.m8n8.x4.shared.b16 {%0,%1,%2,%3}, [%4];"
                 : "=r"(r[0]), "=r"(r[1]), "=r"(r[2]), "=r"(r[3]) : "r"(a));
}
__device__ __forceinline__ void ldsm_x4_t(uint32_t r[4], uint32_t a) {
    asm volatile("ldmatrix.sync.aligned.m8n8.x4.trans.shared.b16 {%0,%1,%2,%3}, [%4];"
                 : "=r"(r[0]), "=r"(r[1]), "=r"(r[2]), "=r"(r[3]) : "r"(a));
}
// bf16 MMA (attention)
__device__ __forceinline__ void mma16816(float c[4], const uint32_t a[4],
                                         uint32_t b0, uint32_t b1) {
    asm volatile("mma.sync.aligned.m16n8k16.row.col.f32.bf16.bf16.f32 "
                 "{%0,%1,%2,%3}, {%4,%5,%6,%7}, {%8,%9}, {%0,%1,%2,%3};"
                 : "+f"(c[0]), "+f"(c[1]), "+f"(c[2]), "+f"(c[3])
                 : "r"(a[0]), "r"(a[1]), "r"(a[2]), "r"(a[3]), "r"(b0), "r"(b1));
}
// fp16 MMA (projections)
__device__ __forceinline__ void mma16816h(float c[4], const uint32_t a[4],
                                          uint32_t b0, uint32_t b1) {
    asm volatile("mma.sync.aligned.m16n8k16.row.col.f32.f16.f16.f32 "
                 "{%0,%1,%2,%3}, {%4,%5,%6,%7}, {%8,%9}, {%0,%1,%2,%3};"
                 : "+f"(c[0]), "+f"(c[1]), "+f"(c[2]), "+f"(c[3])
                 : "r"(a[0]), "r"(a[1]), "r"(a[2]), "r"(a[3]), "r"(b0), "r"(b1));
}
// bf16 split (attention path)
__device__ __forceinline__ void split2(float x0, float x1, uint32_t& hi, uint32_t& lo) {
    asm("cvt.rn.bf16x2.f32 %0, %1, %2;" : "=r"(hi) : "f"(x1), "f"(x0));
    float h0 = __uint_as_float(hi << 16);
    float h1 = __uint_as_float(hi & 0xFFFF0000u);
    float l0 = x0 - h0;
    float l1 = x1 - h1;
    asm("cvt.rn.bf16x2.f32 %0, %1, %2;" : "=r"(lo) : "f"(l1), "f"(l0));
}
// fp16 split (GEMM path): hi = rn16(x), lo = rn16(x - hi)
__device__ __forceinline__ void split2h(float x0, float x1, uint32_t& hi, uint32_t& lo) {
    asm("cvt.rn.f16x2.f32 %0, %1, %2;" : "=r"(hi) : "f"(x1), "f"(x0));
    __half2 hv = *reinterpret_cast<__half2*>(&hi);
    float l0 = x0 - __half2float(__low2half(hv));
    float l1 = x1 - __half2float(__high2half(hv));
    asm("cvt.rn.f16x2.f32 %0, %1, %2;" : "=r"(lo) : "f"(l1), "f"(l0));
}
__device__ __forceinline__ uint32_t pack2h(float x0, float x1) {
    uint32_t r;
    asm("cvt.rn.f16x2.f32 %0, %1, %2;" : "=r"(r) : "f"(x1), "f"(x0));
    return r;
}
__device__ __forceinline__ void cp_async16(uint32_t dst, const void* src) {
    asm volatile("cp.async.cg.shared.global [%0], [%1], 16;" :: "r"(dst), "l"(src));
}
#define CP_COMMIT() asm volatile("cp.async.commit_group;" ::: "memory")
#define CP_WAIT(n)  asm volatile("cp.async.wait_group %0;" :: "n"(n) : "memory")

#define SWZ(o) ((o) ^ (((o) >> 3) & 0x70))

// ===========================================================================
// Conversion passes
// ===========================================================================
__global__ void split_f32h(const float4* __restrict__ src,
                           uint2* __restrict__ hi, uint2* __restrict__ lo, int n4)
{
    int i = blockIdx.x * blockDim.x + threadIdx.x;
    if (i < n4) {
        float4 v = src[i];
        uint32_t h0, l0, h1, l1;
        split2h(v.x, v.y, h0, l0);
        split2h(v.z, v.w, h1, l1);
        hi[i] = make_uint2(h0, h1);
        lo[i] = make_uint2(l0, l1);
    }
}
__global__ void round_f32h(const float4* __restrict__ src,
                           uint2* __restrict__ dst, int n4)
{
    int i = blockIdx.x * blockDim.x + threadIdx.x;
    if (i < n4) {
        float4 v = src[i];
        dst[i] = make_uint2(pack2h(v.x, v.y), pack2h(v.z, v.w));
    }
}

// ===========================================================================
// fp16 2-product GEMM: C = A * B^T, A = Ah + Al (fp16 planes), B single fp16.
// 512 threads / 16 warps (8M x 2N), warp tile 16x64, CTA tile 128x128.
// Stage: A rows 128B [hi 0-63 | lo 64-127] (16KB) + B rows (hi only, 16KB slot).
// 2 stages x 32KB = 64KB. 2-stage cp.async pipeline.
// ===========================================================================
#define KCHUNKS 64
#define GSTAGE  32768
#define GEMM_SMEM (2 * GSTAGE)

__device__ __forceinline__ void gemm_tile_512(
    const __half* __restrict__ Ah, const __half* __restrict__ Al,
    const __half* __restrict__ Bs,
    int m0, int n0, float cacc[8][4], char* smem)
{
    int tid = threadIdx.x;
    int warp = tid >> 5, lane = tid & 31;
    int wm = warp >> 1, wn = warp & 1;          // 8 M-slices x 2 N-slices
    int lr16 = lane & 15, lhalf = (lane >> 4) * 16;
    uint32_t sbase = smem_u32(smem);

    // cp.async mapping: 512 threads; A: 4x16B per row spread over 4 threads
    int ar = tid >> 2;                 // row 0..127
    int aq = (tid & 3) * 32;           // byte offset within 128B row
    int p0 = aq >> 6,        k0 = (aq & 63) >> 1;
    int p1 = (aq + 16) >> 6, k1 = ((aq + 16) & 63) >> 1;
    const __half* a0 = (p0 ? Al : Ah) + (size_t)(m0 + ar) * HID + k0;
    const __half* a1 = (p1 ? Al : Ah) + (size_t)(m0 + ar) * HID + k1;
    bool bact = aq < 64;               // B tile: only bytes 0-63 used
    const __half* b0s = Bs + (size_t)(n0 + ar) * HID + (aq >> 1);
    const __half* b1s = b0s + 8;
    uint32_t d0 = SWZ((uint32_t)ar * 128 + aq);
    uint32_t d1 = SWZ((uint32_t)ar * 128 + aq + 16);

#pragma unroll
    for (int ng = 0; ng < 8; ng++)
#pragma unroll
        for (int i = 0; i < 4; i++) cacc[ng][i] = 0.f;

    auto load_stage = [&](int s, int c) {
        uint32_t st = sbase + s * GSTAGE;
        cp_async16(st + d0, a0 + c * 32);
        cp_async16(st + d1, a1 + c * 32);
        if (bact) {
            cp_async16(st + 16384 + d0, b0s + c * 32);
            cp_async16(st + 16384 + d1, b1s + c * 32);
        }
        CP_COMMIT();
    };

    load_stage(0, 0);
    load_stage(1, 1);

    for (int c = 0; c < KCHUNKS; c++) {
        if (c + 1 < KCHUNKS) CP_WAIT(1); else CP_WAIT(0);
        __syncthreads();

        uint32_t abase = sbase + (c & 1) * GSTAGE;
        uint32_t bbase = abase + 16384;

#pragma unroll
        for (int seg = 0; seg < 2; seg++) {     // Ah*B, Al*B
            int sa = seg * 64;
#pragma unroll
            for (int kk = 0; kk < 2; kk++) {
                uint32_t af[4];
                ldsm_x4(af, abase + SWZ((uint32_t)(wm * 16 + lr16) * 128
                                        + sa + kk * 32 + lhalf));
                uint32_t b0[8], b1[8];
#pragma unroll
                for (int t = 0; t < 4; t++) {
                    uint32_t r[4];
                    ldsm_x4(r, bbase + SWZ((uint32_t)(wn * 64 + t * 16 + lr16) * 128
                                           + kk * 32 + lhalf));
                    b0[2 * t] = r[0]; b0[2 * t + 1] = r[1];
                    b1[2 * t] = r[2]; b1[2 * t + 1] = r[3];
                }
#pragma unroll
                for (int ng = 0; ng < 8; ng++)
                    mma16816h(cacc[ng], af, b0[ng], b1[ng]);
            }
        }
        __syncthreads();
        if (c + 2 < KCHUNKS) load_stage(c & 1, c + 2);
    }
}

__global__ void __launch_bounds__(512, 1) gemm_qkv_mma()
{
    extern __shared__ char smem[];
    int nt = blockIdx.x;
    int m0 = blockIdx.y * 128;

    const __half* Bs; float* dst_base; int h, nkvh;
    if (nt < 16)      { Bs = g_wqs; h = nt;      dst_base = g_q; nkvh = NH;  }
    else if (nt < 20) { Bs = g_wks; h = nt - 16; dst_base = g_k; nkvh = NKV; }
    else              { Bs = g_wvs; h = nt - 20; dst_base = g_v; nkvh = NKV; }

    float cacc[8][4];
    gemm_tile_512(g_xh, g_xl, Bs, m0, h * HD, cacc, smem);

    int tid = threadIdx.x;
    int warp = tid >> 5, lane = tid & 31;
    int wm = warp >> 1, wn = warp & 1;
    int r0 = lane >> 2, c0 = (lane & 3) * 2;

#pragma unroll
    for (int ng = 0; ng < 8; ng++) {
        int col = wn * 64 + ng * 8 + c0;
#pragma unroll
        for (int half = 0; half < 2; half++) {
            int mg = m0 + wm * 16 + r0 + half * 8;
            int b = mg >> 11, s = mg & (S_LEN - 1);
            float* d = dst_base + ((size_t)(b * nkvh + h) * S_LEN + s) * HD + col;
            *(float2*)d = make_float2(cacc[ng][2 * half], cacc[ng][2 * half + 1]);
        }
    }
}

__global__ void __launch_bounds__(512, 1) gemm_wo_mma(float* __restrict__ out)
{
    extern __shared__ char smem[];
    int n0 = blockIdx.x * 128;
    int m0 = blockIdx.y * 128;

    float cacc[8][4];
    gemm_tile_512(g_aoh, g_aol, g_wos, m0, n0, cacc, smem);

    int tid = threadIdx.x;
    int warp = tid >> 5, lane = tid & 31;
    int wm = warp >> 1, wn = warp & 1;
    int r0 = lane >> 2, c0 = (lane & 3) * 2;

#pragma unroll
    for (int ng = 0; ng < 8; ng++) {
        int col = n0 + wn * 64 + ng * 8 + c0;
#pragma unroll
        for (int half = 0; half < 2; half++) {
            int mg = m0 + wm * 16 + r0 + half * 8;
            *(float2*)&out[(size_t)mg * HID + col] =
                make_float2(cacc[ng][2 * half], cacc[ng][2 * half + 1]);
        }
    }
}

// ---------------------------------------------------------------------------
// RoPE (in place, fp32). 256 threads = 4 rows per block.
// ---------------------------------------------------------------------------
__device__ __forceinline__ void rope_rows(float* g)
{
    int r = blockIdx.x * 4 + (threadIdx.x >> 6);
    int d = threadIdx.x & 63;
    float* base = g + (size_t)r * HD;
    int s = r & (S_LEN - 1);
    float inv = (float)exp2(-(double)d * 0.20762050593046747);
    float ang = (float)s * inv;
    float sn, cs;
    sincosf(ang, &sn, &cs);
    float x1 = base[d], x2 = base[d + 64];
    base[d]      = x1 * cs - x2 * sn;
    base[d + 64] = x1 * sn + x2 * cs;
}
__global__ void rope_q() { rope_rows(g_q); }
__global__ void rope_k() { rope_rows(g_k); }

// ===========================================================================
// HMMA flash attention (R5/R7 verbatim — known 605us, bf16 3-product)
// BM=128 (8 warps x m16), BN=64 keys/tile. 256 threads.
// ===========================================================================
#define AT_QH 0
#define AT_QL 32768
#define AT_KH 65536
#define AT_KL 81920
#define AT_VH 98304
#define AT_VL 114688
#define ATTN_SMEM 131072

__global__ void __launch_bounds__(256, 1) attn_mma(const float* __restrict__ kw)
{
    extern __shared__ char smem[];
    uint32_t sb = smem_u32(smem);

    int tid = threadIdx.x;
    int wq = tid >> 5, lane = tid & 31;
    int lr16 = lane & 15;
    int lhalf = (lane >> 4) * 16;

    int mt = blockIdx.x, h = blockIdx.y, b = blockIdx.z;
    int m0 = mt * 128;
    int kh = h >> 2;
    float scale = kw[h] * 0.08838834764831845f;

    const float* qg = g_q + ((size_t)(b * NH  + h ) * S_LEN + m0) * HD;
    const float* kg = g_k + ((size_t)(b * NKV + kh) * S_LEN) * HD;
    const float* vg = g_v + ((size_t)(b * NKV + kh) * S_LEN) * HD;

    {
        int row = tid >> 1;
        int dst = (tid & 1) * 64;
        const float* src = qg + (size_t)row * HD + dst;
        char* qh = smem + AT_QH + (dst >> 6) * 16384;
        char* ql = smem + AT_QL + (dst >> 6) * 16384;
#pragma unroll
        for (int j = 0; j < 16; j++) {
            float4 v = *(const float4*)(src + j * 4);
            v.x *= scale; v.y *= scale; v.z *= scale; v.w *= scale;
            uint32_t h0, l0, h1, l1;
            split2(v.x, v.y, h0, l0);
            split2(v.z, v.w, h1, l1);
            uint32_t off = (uint32_t)row * 128 + ((dst + j * 4) & 63) * 2;
            *(uint2*)(qh + SWZ(off)) = make_uint2(h0, h1);
            *(uint2*)(ql + SWZ(off)) = make_uint2(l0, l1);
        }
    }

    float m1 = -1e30f, m2 = -1e30f, l1s = 0.f, l2s = 0.f;
    float oacc[16][4];
#pragma unroll
    for (int ng = 0; ng < 16; ng++)
#pragma unroll
        for (int i = 0; i < 4; i++) oacc[ng][i] = 0.f;

    int vrow_off = (lane & 7) + ((lane >> 3) & 1) * 8;
    int vcol8 = (lane >> 4) * 8;

    int ntiles = 2 * mt + 2;
    for (int nt = 0; nt < ntiles; nt++) {
        int n0 = nt * 64;
        __syncthreads();

        {
            int row = tid >> 2;
            int dst = (tid & 3) * 32;
            int half = dst >> 6;
            const float* ks = kg + (size_t)(n0 + row) * HD + dst;
            const float* vs = vg + (size_t)(n0 + row) * HD + dst;
            char* kh_t = smem + AT_KH + half * 8192;
            char* kl_t = smem + AT_KL + half * 8192;
            char* vh_t = smem + AT_VH + half * 8192;
            char* vl_t = smem + AT_VL + half * 8192;
#pragma unroll
            for (int j = 0; j < 8; j++) {
                uint32_t off = SWZ((uint32_t)row * 128 + ((dst + j * 4) & 63) * 2);
                float4 v = *(const float4*)(ks + j * 4);
                uint32_t h0, l0, h1, l1;
                split2(v.x, v.y, h0, l0);
                split2(v.z, v.w, h1, l1);
                *(uint2*)(kh_t + off) = make_uint2(h0, h1);
                *(uint2*)(kl_t + off) = make_uint2(l0, l1);
                v = *(const float4*)(vs + j * 4);
                split2(v.x, v.y, h0, l0);
                split2(v.z, v.w, h1, l1);
                *(uint2*)(vh_t + off) = make_uint2(h0, h1);
                *(uint2*)(vl_t + off) = make_uint2(l0, l1);
            }
        }
        __syncthreads();

        float sacc[8][4];
#pragma unroll
        for (int ng = 0; ng < 8; ng++)
#pragma unroll
            for (int i = 0; i < 4; i++) sacc[ng][i] = 0.f;

#pragma unroll
        for (int seg = 0; seg < 3; seg++) {
            uint32_t qbase = sb + ((seg == 1) ? AT_QL : AT_QH);
            uint32_t kbase = sb + ((seg == 2) ? AT_KL : AT_KH);
#pragma unroll
            for (int ks = 0; ks < 8; ks++) {
                int half = ks >> 2;
                uint32_t koff = (ks & 3) * 32 + lhalf;
                uint32_t af[4];
                ldsm_x4(af, qbase + half * 16384
                            + SWZ((uint32_t)(wq * 16 + lr16) * 128 + koff));
                uint32_t b0[8], b1[8];
#pragma unroll
                for (int t = 0; t < 4; t++) {
                    uint32_t r[4];
                    ldsm_x4(r, kbase + half * 8192
                               + SWZ((uint32_t)(t * 16 + lr16) * 128 + koff));
                    b0[2 * t] = r[0]; b0[2 * t + 1] = r[1];
                    b1[2 * t] = r[2]; b1[2 * t + 1] = r[3];
                }
#pragma unroll
                for (int ng = 0; ng < 8; ng++)
                    mma16816(sacc[ng], af, b0[ng], b1[ng]);
            }
        }

        if (nt >= 2 * mt) {
            int rg1 = m0 + wq * 16 + (lane >> 2);
            int rg2 = rg1 + 8;
            int cb = n0 + (lane & 3) * 2;
#pragma unroll
            for (int ng = 0; ng < 8; ng++) {
                int c0g = cb + ng * 8;
                if (c0g > rg1)     sacc[ng][0] = -1e30f;
                if (c0g + 1 > rg1) sacc[ng][1] = -1e30f;
                if (c0g > rg2)     sacc[ng][2] = -1e30f;
                if (c0g + 1 > rg2) sacc[ng][3] = -1e30f;
            }
        }

        float rmax1 = -1e30f, rmax2 = -1e30f;
#pragma unroll
        for (int ng = 0; ng < 8; ng++) {
            rmax1 = fmaxf(rmax1, fmaxf(sacc[ng][0], sacc[ng][1]));
            rmax2 = fmaxf(rmax2, fmaxf(sacc[ng][2], sacc[ng][3]));
        }
        rmax1 = fmaxf(rmax1, __shfl_xor_sync(0xffffffffu, rmax1, 1));
        rmax1 = fmaxf(rmax1, __shfl_xor_sync(0xffffffffu, rmax1, 2));
        rmax2 = fmaxf(rmax2, __shfl_xor_sync(0xffffffffu, rmax2, 1));
        rmax2 = fmaxf(rmax2, __shfl_xor_sync(0xffffffffu, rmax2, 2));

        float mn1 = fmaxf(m1, rmax1);
        float mn2 = fmaxf(m2, rmax2);
        float alpha1 = __expf(m1 - mn1);
        float alpha2 = __expf(m2 - mn2);
        m1 = mn1; m2 = mn2;

        float rsum1 = 0.f, rsum2 = 0.f;
#pragma unroll
        for (int ng = 0; ng < 8; ng++) {
            sacc[ng][0] = __expf(sacc[ng][0] - mn1);
            sacc[ng][1] = __expf(sacc[ng][1] - mn1);
            sacc[ng][2] = __expf(sacc[ng][2] - mn2);
            sacc[ng][3] = __expf(sacc[ng][3] - mn2);
            rsum1 += sacc[ng][0] + sacc[ng][1];
            rsum2 += sacc[ng][2] + sacc[ng][3];
        }
        rsum1 += __shfl_xor_sync(0xffffffffu, rsum1, 1);
        rsum1 += __shfl_xor_sync(0xffffffffu, rsum1, 2);
        rsum2 += __shfl_xor_sync(0xffffffffu, rsum2, 1);
        rsum2 += __shfl_xor_sync(0xffffffffu, rsum2, 2);
        l1s = l1s * alpha1 + rsum1;
        l2s = l2s * alpha2 + rsum2;

#pragma unroll
        for (int ng = 0; ng < 16; ng++) {
            oacc[ng][0] *= alpha1; oacc[ng][1] *= alpha1;
            oacc[ng][2] *= alpha2; oacc[ng][3] *= alpha2;
        }

#pragma unroll
        for (int ks = 0; ks < 4; ks++) {
            uint32_t pha[4], pla[4];
            split2(sacc[2 * ks][0],     sacc[2 * ks][1],     pha[0], pla[0]);
            split2(sacc[2 * ks][2],     sacc[2 * ks][3],     pha[1], pla[1]);
            split2(sacc[2 * ks + 1][0], sacc[2 * ks + 1][1], pha[2], pla[2]);
            split2(sacc[2 * ks + 1][2], sacc[2 * ks + 1][3], pha[3], pla[3]);

            uint32_t vrow = (uint32_t)(ks * 16 + vrow_off) * 128;
#pragma unroll
            for (int t = 0; t < 8; t++) {
                int half = t >> 2;
                uint32_t coff = ((t & 3) * 16 + vcol8) * 2;
                uint32_t r[4];
                ldsm_x4_t(r, sb + AT_VH + half * 8192 + SWZ(vrow + coff));
                mma16816(oacc[2 * t],     pha, r[0], r[1]);
                mma16816(oacc[2 * t + 1], pha, r[2], r[3]);
                mma16816(oacc[2 * t],     pla, r[0], r[1]);
                mma16816(oacc[2 * t + 1], pla, r[2], r[3]);
            }
#pragma unroll
            for (int t = 0; t < 8; t++) {
                int half = t >> 2;
                uint32_t coff = ((t & 3) * 16 + vcol8) * 2;
                uint32_t r[4];
                ldsm_x4_t(r, sb + AT_VL + half * 8192 + SWZ(vrow + coff));
                mma16816(oacc[2 * t],     pha, r[0], r[1]);
                mma16816(oacc[2 * t + 1], pha, r[2], r[3]);
            }
        }
    }

    float inv1 = 1.0f / l1s;
    float inv2 = 1.0f / l2s;
    int r1 = m0 + wq * 16 + (lane >> 2);
    int c0 = (lane & 3) * 2;
    float* dst1 = g_ao + ((size_t)(b * S_LEN + r1)) * HID + h * HD;
    float* dst2 = g_ao + ((size_t)(b * S_LEN + r1 + 8)) * HID + h * HD;
#pragma unroll
    for (int ng = 0; ng < 16; ng++) {
        int d = ng * 8 + c0;
        *(float2*)(dst1 + d) = make_float2(oacc[ng][0] * inv1, oacc[ng][1] * inv1);
        *(float2*)(dst2 + d) = make_float2(oacc[ng][2] * inv2, oacc[ng][3] * inv2);
    }
}

// ---------------------------------------------------------------------------
// Launch
// ---------------------------------------------------------------------------
extern "C" void kernel_launch(void* const* d_in, const int* in_sizes, int n_in,
                              void* d_out, int out_size)
{
    const float* x  = (const float*)d_in[0];
    const float* wq = (const float*)d_in[1];
    const float* wk = (const float*)d_in[2];
    const float* wv = (const float*)d_in[3];
    const float* wo = (const float*)d_in[4];
    const float* kw = (const float*)d_in[5];
    float* out = (float*)d_out;

    cudaFuncSetAttribute(attn_mma, cudaFuncAttributeMaxDynamicSharedMemorySize,
                         ATTN_SMEM);
    cudaFuncSetAttribute(gemm_qkv_mma, cudaFuncAttributeMaxDynamicSharedMemorySize,
                         GEMM_SMEM);
    cudaFuncSetAttribute(gemm_wo_mma, cudaFuncAttributeMaxDynamicSharedMemorySize,
                         GEMM_SMEM);

    void *xh, *xl, *wqs, *wks, *wvs, *wos, *ao, *aoh, *aol;
    cudaGetSymbolAddress(&xh, g_xh);   cudaGetSymbolAddress(&xl, g_xl);
    cudaGetSymbolAddress(&wqs, g_wqs); cudaGetSymbolAddress(&wks, g_wks);
    cudaGetSymbolAddress(&wvs, g_wvs); cudaGetSymbolAddress(&wos, g_wos);
    cudaGetSymbolAddress(&ao, g_ao);
    cudaGetSymbolAddress(&aoh, g_aoh); cudaGetSymbolAddress(&aol, g_aol);

    auto splith = [&](const float* src, void* hi, void* lo, size_t n) {
        int n4 = (int)(n / 4);
        split_f32h<<<(n4 + 255) / 256, 256>>>((const float4*)src,
                                              (uint2*)hi, (uint2*)lo, n4);
    };
    auto roundh = [&](const float* src, void* dst, size_t n) {
        int n4 = (int)(n / 4);
        round_f32h<<<(n4 + 255) / 256, 256>>>((const float4*)src, (uint2*)dst, n4);
    };

    // presplit activations; round weights to single fp16
    splith(x, xh, xl, (size_t)MROWS * HID);
    roundh(wq, wqs, (size_t)2048 * HID);
    roundh(wk, wks, (size_t)512 * HID);
    roundh(wv, wvs, (size_t)512 * HID);
    roundh(wo, wos, (size_t)2048 * HID);

    // QKV projection (fp16 2-product)
    gemm_qkv_mma<<<dim3(24, 32), 512, GEMM_SMEM>>>();

    // RoPE (fp32, in place)
    rope_q<<<BATCH * NH * S_LEN / 4, 256>>>();
    rope_k<<<BATCH * NKV * S_LEN / 4, 256>>>();

    // Attention (bf16 3-product, unchanged)
    attn_mma<<<dim3(S_LEN / 128, NH, BATCH), 256, ATTN_SMEM>>>(kw);

    // presplit attention output for the WO GEMM
    splith((const float*)ao, aoh, aol, (size_t)MROWS * HID);

    // Output projection (fp16 2-product)
    gemm_wo_mma<<<dim3(16, 32), 512, GEMM_SMEM>>>(out);
}

// round 10
// speedup vs baseline: 1.5193x; 1.0928x over previous
#include <cuda_runtime.h>
#include <cuda_bf16.h>
#include <cuda_fp16.h>
#include <math.h>
#include <cstdint>

#define S_LEN 2048
#define HID   2048
#define NH    16
#define NKV   4
#define HD    128
#define BATCH 2
#define MROWS (BATCH * S_LEN)          // 4096

// ---------------- fp32 scratch ----------------
__device__ float g_q[(size_t)BATCH * NH  * S_LEN * HD];   // [b][h][s][d]
__device__ float g_k[(size_t)BATCH * NKV * S_LEN * HD];
__device__ float g_v[(size_t)BATCH * NKV * S_LEN * HD];
__device__ float g_ao[(size_t)MROWS * HID];               // [b][s][h*128+d]

// ---------------- presplit fp16 scratch ----------------
__device__ __half g_xh[(size_t)MROWS * HID],  g_xl[(size_t)MROWS * HID];
__device__ __half g_aoh[(size_t)MROWS * HID], g_aol[(size_t)MROWS * HID];
__device__ __half g_wqs[(size_t)2048 * HID];
__device__ __half g_wks[(size_t)512  * HID];
__device__ __half g_wvs[(size_t)512  * HID];
__device__ __half g_wos[(size_t)2048 * HID];

// ===========================================================================
// Helpers
// ===========================================================================
__device__ __forceinline__ uint32_t smem_u32(const void* p) {
    uint32_t a;
    asm("{ .reg .u64 t; cvta.to.shared.u64 t, %1; cvt.u32.u64 %0, t; }"
        : "=r"(a) : "l"(p));
    return a;
}
__device__ __forceinline__ void ldsm_x4(uint32_t r[4], uint32_t a) {
    asm volatile("ldmatrix.sync.aligned.m8n8.x4.shared.b16 {%0,%1,%2,%3}, [%4];"
                 : "=r"(r[0]), "=r"(r[1]), "=r"(r[2]), "=r"(r[3]) : "r"(a));
}
__device__ __forceinline__ void ldsm_x4_t(uint32_t r[4], uint32_t a) {
    asm volatile("ldmatrix.sync.aligned.m8n8.x4.trans.shared.b16 {%0,%1,%2,%3}, [%4];"
                 : "=r"(r[0]), "=r"(r[1]), "=r"(r[2]), "=r"(r[3]) : "r"(a));
}
// fp16 MMA
__device__ __forceinline__ void mma16816h(float c[4], const uint32_t a[4],
                                          uint32_t b0, uint32_t b1) {
    asm volatile("mma.sync.aligned.m16n8k16.row.col.f32.f16.f16.f32 "
                 "{%0,%1,%2,%3}, {%4,%5,%6,%7}, {%8,%9}, {%0,%1,%2,%3};"
                 : "+f"(c[0]), "+f"(c[1]), "+f"(c[2]), "+f"(c[3])
                 : "r"(a[0]), "r"(a[1]), "r"(a[2]), "r"(a[3]), "r"(b0), "r"(b1));
}
// fp16 split: hi = rn16(x), lo = rn16(x - hi)
__device__ __forceinline__ void split2h(float x0, float x1, uint32_t& hi, uint32_t& lo) {
    asm("cvt.rn.f16x2.f32 %0, %1, %2;" : "=r"(hi) : "f"(x1), "f"(x0));
    __half2 hv = *reinterpret_cast<__half2*>(&hi);
    float l0 = x0 - __half2float(__low2half(hv));
    float l1 = x1 - __half2float(__high2half(hv));
    asm("cvt.rn.f16x2.f32 %0, %1, %2;" : "=r"(lo) : "f"(l1), "f"(l0));
}
__device__ __forceinline__ uint32_t pack2h(float x0, float x1) {
    uint32_t r;
    asm("cvt.rn.f16x2.f32 %0, %1, %2;" : "=r"(r) : "f"(x1), "f"(x0));
    return r;
}
__device__ __forceinline__ void cp_async16(uint32_t dst, const void* src) {
    asm volatile("cp.async.cg.shared.global [%0], [%1], 16;" :: "r"(dst), "l"(src));
}
#define CP_COMMIT() asm volatile("cp.async.commit_group;" ::: "memory")
#define CP_WAIT(n)  asm volatile("cp.async.wait_group %0;" :: "n"(n) : "memory")

#define SWZ(o) ((o) ^ (((o) >> 3) & 0x70))

// ===========================================================================
// Conversion passes
// ===========================================================================
__global__ void split_f32h(const float4* __restrict__ src,
                           uint2* __restrict__ hi, uint2* __restrict__ lo, int n4)
{
    int i = blockIdx.x * blockDim.x + threadIdx.x;
    if (i < n4) {
        float4 v = src[i];
        uint32_t h0, l0, h1, l1;
        split2h(v.x, v.y, h0, l0);
        split2h(v.z, v.w, h1, l1);
        hi[i] = make_uint2(h0, h1);
        lo[i] = make_uint2(l0, l1);
    }
}
__global__ void round_f32h(const float4* __restrict__ src,
                           uint2* __restrict__ dst, int n4)
{
    int i = blockIdx.x * blockDim.x + threadIdx.x;
    if (i < n4) {
        float4 v = src[i];
        dst[i] = make_uint2(pack2h(v.x, v.y), pack2h(v.z, v.w));
    }
}

// ===========================================================================
// fp16 2-product GEMM (R9 verbatim — at HMMA roofline)
// ===========================================================================
#define KCHUNKS 64
#define GSTAGE  32768
#define GEMM_SMEM (2 * GSTAGE)

__device__ __forceinline__ void gemm_tile_512(
    const __half* __restrict__ Ah, const __half* __restrict__ Al,
    const __half* __restrict__ Bs,
    int m0, int n0, float cacc[8][4], char* smem)
{
    int tid = threadIdx.x;
    int warp = tid >> 5, lane = tid & 31;
    int wm = warp >> 1, wn = warp & 1;
    int lr16 = lane & 15, lhalf = (lane >> 4) * 16;
    uint32_t sbase = smem_u32(smem);

    int ar = tid >> 2;
    int aq = (tid & 3) * 32;
    int p0 = aq >> 6,        k0 = (aq & 63) >> 1;
    int p1 = (aq + 16) >> 6, k1 = ((aq + 16) & 63) >> 1;
    const __half* a0 = (p0 ? Al : Ah) + (size_t)(m0 + ar) * HID + k0;
    const __half* a1 = (p1 ? Al : Ah) + (size_t)(m0 + ar) * HID + k1;
    bool bact = aq < 64;
    const __half* b0s = Bs + (size_t)(n0 + ar) * HID + (aq >> 1);
    const __half* b1s = b0s + 8;
    uint32_t d0 = SWZ((uint32_t)ar * 128 + aq);
    uint32_t d1 = SWZ((uint32_t)ar * 128 + aq + 16);

#pragma unroll
    for (int ng = 0; ng < 8; ng++)
#pragma unroll
        for (int i = 0; i < 4; i++) cacc[ng][i] = 0.f;

    auto load_stage = [&](int s, int c) {
        uint32_t st = sbase + s * GSTAGE;
        cp_async16(st + d0, a0 + c * 32);
        cp_async16(st + d1, a1 + c * 32);
        if (bact) {
            cp_async16(st + 16384 + d0, b0s + c * 32);
            cp_async16(st + 16384 + d1, b1s + c * 32);
        }
        CP_COMMIT();
    };

    load_stage(0, 0);
    load_stage(1, 1);

    for (int c = 0; c < KCHUNKS; c++) {
        if (c + 1 < KCHUNKS) CP_WAIT(1); else CP_WAIT(0);
        __syncthreads();

        uint32_t abase = sbase + (c & 1) * GSTAGE;
        uint32_t bbase = abase + 16384;

#pragma unroll
        for (int seg = 0; seg < 2; seg++) {
            int sa = seg * 64;
#pragma unroll
            for (int kk = 0; kk < 2; kk++) {
                uint32_t af[4];
                ldsm_x4(af, abase + SWZ((uint32_t)(wm * 16 + lr16) * 128
                                        + sa + kk * 32 + lhalf));
                uint32_t b0[8], b1[8];
#pragma unroll
                for (int t = 0; t < 4; t++) {
                    uint32_t r[4];
                    ldsm_x4(r, bbase + SWZ((uint32_t)(wn * 64 + t * 16 + lr16) * 128
                                           + kk * 32 + lhalf));
                    b0[2 * t] = r[0]; b0[2 * t + 1] = r[1];
                    b1[2 * t] = r[2]; b1[2 * t + 1] = r[3];
                }
#pragma unroll
                for (int ng = 0; ng < 8; ng++)
                    mma16816h(cacc[ng], af, b0[ng], b1[ng]);
            }
        }
        __syncthreads();
        if (c + 2 < KCHUNKS) load_stage(c & 1, c + 2);
    }
}

__global__ void __launch_bounds__(512, 1) gemm_qkv_mma()
{
    extern __shared__ char smem[];
    int nt = blockIdx.x;
    int m0 = blockIdx.y * 128;

    const __half* Bs; float* dst_base; int h, nkvh;
    if (nt < 16)      { Bs = g_wqs; h = nt;      dst_base = g_q; nkvh = NH;  }
    else if (nt < 20) { Bs = g_wks; h = nt - 16; dst_base = g_k; nkvh = NKV; }
    else              { Bs = g_wvs; h = nt - 20; dst_base = g_v; nkvh = NKV; }

    float cacc[8][4];
    gemm_tile_512(g_xh, g_xl, Bs, m0, h * HD, cacc, smem);

    int tid = threadIdx.x;
    int warp = tid >> 5, lane = tid & 31;
    int wm = warp >> 1, wn = warp & 1;
    int r0 = lane >> 2, c0 = (lane & 3) * 2;

#pragma unroll
    for (int ng = 0; ng < 8; ng++) {
        int col = wn * 64 + ng * 8 + c0;
#pragma unroll
        for (int half = 0; half < 2; half++) {
            int mg = m0 + wm * 16 + r0 + half * 8;
            int b = mg >> 11, s = mg & (S_LEN - 1);
            float* d = dst_base + ((size_t)(b * nkvh + h) * S_LEN + s) * HD + col;
            *(float2*)d = make_float2(cacc[ng][2 * half], cacc[ng][2 * half + 1]);
        }
    }
}

__global__ void __launch_bounds__(512, 1) gemm_wo_mma(float* __restrict__ out)
{
    extern __shared__ char smem[];
    int n0 = blockIdx.x * 128;
    int m0 = blockIdx.y * 128;

    float cacc[8][4];
    gemm_tile_512(g_aoh, g_aol, g_wos, m0, n0, cacc, smem);

    int tid = threadIdx.x;
    int warp = tid >> 5, lane = tid & 31;
    int wm = warp >> 1, wn = warp & 1;
    int r0 = lane >> 2, c0 = (lane & 3) * 2;

#pragma unroll
    for (int ng = 0; ng < 8; ng++) {
        int col = n0 + wn * 64 + ng * 8 + c0;
#pragma unroll
        for (int half = 0; half < 2; half++) {
            int mg = m0 + wm * 16 + r0 + half * 8;
            *(float2*)&out[(size_t)mg * HID + col] =
                make_float2(cacc[ng][2 * half], cacc[ng][2 * half + 1]);
        }
    }
}

// ---------------------------------------------------------------------------
// RoPE (in place, fp32). 256 threads = 4 rows per block.
// ---------------------------------------------------------------------------
__device__ __forceinline__ void rope_rows(float* g)
{
    int r = blockIdx.x * 4 + (threadIdx.x >> 6);
    int d = threadIdx.x & 63;
    float* base = g + (size_t)r * HD;
    int s = r & (S_LEN - 1);
    float inv = (float)exp2(-(double)d * 0.20762050593046747);
    float ang = (float)s * inv;
    float sn, cs;
    sincosf(ang, &sn, &cs);
    float x1 = base[d], x2 = base[d + 64];
    base[d]      = x1 * cs - x2 * sn;
    base[d + 64] = x1 * sn + x2 * cs;
}
__global__ void rope_q() { rope_rows(g_q); }
__global__ void rope_k() { rope_rows(g_k); }

// ===========================================================================
// HMMA flash attention, fp16 2-product both matmuls.
// BM=128 (8 warps x m16), BN=64 keys/tile, 256 threads.
// SMEM: QH 32K | QL 32K | K 16K | V 16K = 96KB
//   Q planes: two 16K halves by d (0-63, 64-127), rows of 128B.
//   K/V: single fp16 plane, two 8K halves by d, rows of 128B.
// S = Qh*K + Ql*K;  O += Ph*V + Pl*V.
// ===========================================================================
#define AT_QH 0
#define AT_QL 32768
#define AT_K  65536
#define AT_V  81920
#define ATTN_SMEM 98304

__global__ void __launch_bounds__(256, 1) attn_mma(const float* __restrict__ kw)
{
    extern __shared__ char smem[];
    uint32_t sb = smem_u32(smem);

    int tid = threadIdx.x;
    int wq = tid >> 5, lane = tid & 31;
    int lr16 = lane & 15;
    int lhalf = (lane >> 4) * 16;

    int mt = blockIdx.x, h = blockIdx.y, b = blockIdx.z;
    int m0 = mt * 128;
    int kh = h >> 2;
    float scale = kw[h] * 0.08838834764831845f;

    const float* qg = g_q + ((size_t)(b * NH  + h ) * S_LEN + m0) * HD;
    const float* kg = g_k + ((size_t)(b * NKV + kh) * S_LEN) * HD;
    const float* vg = g_v + ((size_t)(b * NKV + kh) * S_LEN) * HD;

    // ---- load + convert + scale Q (fp16 hi/lo) ----
    {
        int row = tid >> 1;
        int dst = (tid & 1) * 64;
        const float* src = qg + (size_t)row * HD + dst;
        char* qh = smem + AT_QH + (dst >> 6) * 16384;
        char* ql = smem + AT_QL + (dst >> 6) * 16384;
#pragma unroll
        for (int j = 0; j < 16; j++) {
            float4 v = *(const float4*)(src + j * 4);
            v.x *= scale; v.y *= scale; v.z *= scale; v.w *= scale;
            uint32_t h0, l0, h1, l1;
            split2h(v.x, v.y, h0, l0);
            split2h(v.z, v.w, h1, l1);
            uint32_t off = (uint32_t)row * 128 + ((dst + j * 4) & 63) * 2;
            *(uint2*)(qh + SWZ(off)) = make_uint2(h0, h1);
            *(uint2*)(ql + SWZ(off)) = make_uint2(l0, l1);
        }
    }

    float m1 = -1e30f, m2 = -1e30f, l1s = 0.f, l2s = 0.f;
    float oacc[16][4];
#pragma unroll
    for (int ng = 0; ng < 16; ng++)
#pragma unroll
        for (int i = 0; i < 4; i++) oacc[ng][i] = 0.f;

    int vrow_off = (lane & 7) + ((lane >> 3) & 1) * 8;
    int vcol8 = (lane >> 4) * 8;

    int ntiles = 2 * mt + 2;
    for (int nt = 0; nt < ntiles; nt++) {
        int n0 = nt * 64;
        __syncthreads();

        // ---- load + convert K, V tiles (single fp16 plane each) ----
        {
            int row = tid >> 2;
            int dst = (tid & 3) * 32;
            int half = dst >> 6;
            const float* ks = kg + (size_t)(n0 + row) * HD + dst;
            const float* vs = vg + (size_t)(n0 + row) * HD + dst;
            char* k_t = smem + AT_K + half * 8192;
            char* v_t = smem + AT_V + half * 8192;
#pragma unroll
            for (int j = 0; j < 8; j++) {
                uint32_t off = SWZ((uint32_t)row * 128 + ((dst + j * 4) & 63) * 2);
                float4 v = *(const float4*)(ks + j * 4);
                *(uint2*)(k_t + off) = make_uint2(pack2h(v.x, v.y), pack2h(v.z, v.w));
                v = *(const float4*)(vs + j * 4);
                *(uint2*)(v_t + off) = make_uint2(pack2h(v.x, v.y), pack2h(v.z, v.w));
            }
        }
        __syncthreads();

        // ---- S = Q K^T (Qh*K + Ql*K) ----
        float sacc[8][4];
#pragma unroll
        for (int ng = 0; ng < 8; ng++)
#pragma unroll
            for (int i = 0; i < 4; i++) sacc[ng][i] = 0.f;

#pragma unroll
        for (int seg = 0; seg < 2; seg++) {
            uint32_t qbase = sb + ((seg == 1) ? AT_QL : AT_QH);
#pragma unroll
            for (int ks = 0; ks < 8; ks++) {
                int half = ks >> 2;
                uint32_t koff = (ks & 3) * 32 + lhalf;
                uint32_t af[4];
                ldsm_x4(af, qbase + half * 16384
                            + SWZ((uint32_t)(wq * 16 + lr16) * 128 + koff));
                uint32_t b0[8], b1[8];
#pragma unroll
                for (int t = 0; t < 4; t++) {
                    uint32_t r[4];
                    ldsm_x4(r, sb + AT_K + half * 8192
                               + SWZ((uint32_t)(t * 16 + lr16) * 128 + koff));
                    b0[2 * t] = r[0]; b0[2 * t + 1] = r[1];
                    b1[2 * t] = r[2]; b1[2 * t + 1] = r[3];
                }
#pragma unroll
                for (int ng = 0; ng < 8; ng++)
                    mma16816h(sacc[ng], af, b0[ng], b1[ng]);
            }
        }

        // ---- causal mask (last two tiles only) ----
        if (nt >= 2 * mt) {
            int rg1 = m0 + wq * 16 + (lane >> 2);
            int rg2 = rg1 + 8;
            int cb = n0 + (lane & 3) * 2;
#pragma unroll
            for (int ng = 0; ng < 8; ng++) {
                int c0g = cb + ng * 8;
                if (c0g > rg1)     sacc[ng][0] = -1e30f;
                if (c0g + 1 > rg1) sacc[ng][1] = -1e30f;
                if (c0g > rg2)     sacc[ng][2] = -1e30f;
                if (c0g + 1 > rg2) sacc[ng][3] = -1e30f;
            }
        }

        // ---- online softmax ----
        float rmax1 = -1e30f, rmax2 = -1e30f;
#pragma unroll
        for (int ng = 0; ng < 8; ng++) {
            rmax1 = fmaxf(rmax1, fmaxf(sacc[ng][0], sacc[ng][1]));
            rmax2 = fmaxf(rmax2, fmaxf(sacc[ng][2], sacc[ng][3]));
        }
        rmax1 = fmaxf(rmax1, __shfl_xor_sync(0xffffffffu, rmax1, 1));
        rmax1 = fmaxf(rmax1, __shfl_xor_sync(0xffffffffu, rmax1, 2));
        rmax2 = fmaxf(rmax2, __shfl_xor_sync(0xffffffffu, rmax2, 1));
        rmax2 = fmaxf(rmax2, __shfl_xor_sync(0xffffffffu, rmax2, 2));

        float mn1 = fmaxf(m1, rmax1);
        float mn2 = fmaxf(m2, rmax2);
        float alpha1 = __expf(m1 - mn1);
        float alpha2 = __expf(m2 - mn2);
        m1 = mn1; m2 = mn2;

        float rsum1 = 0.f, rsum2 = 0.f;
#pragma unroll
        for (int ng = 0; ng < 8; ng++) {
            sacc[ng][0] = __expf(sacc[ng][0] - mn1);
            sacc[ng][1] = __expf(sacc[ng][1] - mn1);
            sacc[ng][2] = __expf(sacc[ng][2] - mn2);
            sacc[ng][3] = __expf(sacc[ng][3] - mn2);
            rsum1 += sacc[ng][0] + sacc[ng][1];
            rsum2 += sacc[ng][2] + sacc[ng][3];
        }
        rsum1 += __shfl_xor_sync(0xffffffffu, rsum1, 1);
        rsum1 += __shfl_xor_sync(0xffffffffu, rsum1, 2);
        rsum2 += __shfl_xor_sync(0xffffffffu, rsum2, 1);
        rsum2 += __shfl_xor_sync(0xffffffffu, rsum2, 2);
        l1s = l1s * alpha1 + rsum1;
        l2s = l2s * alpha2 + rsum2;

#pragma unroll
        for (int ng = 0; ng < 16; ng++) {
            oacc[ng][0] *= alpha1; oacc[ng][1] *= alpha1;
            oacc[ng][2] *= alpha2; oacc[ng][3] *= alpha2;
        }

        // ---- O += P V (Ph*V + Pl*V), P split in registers ----
#pragma unroll
        for (int ks = 0; ks < 4; ks++) {
            uint32_t pha[4], pla[4];
            split2h(sacc[2 * ks][0],     sacc[2 * ks][1],     pha[0], pla[0]);
            split2h(sacc[2 * ks][2],     sacc[2 * ks][3],     pha[1], pla[1]);
            split2h(sacc[2 * ks + 1][0], sacc[2 * ks + 1][1], pha[2], pla[2]);
            split2h(sacc[2 * ks + 1][2], sacc[2 * ks + 1][3], pha[3], pla[3]);

            uint32_t vrow = (uint32_t)(ks * 16 + vrow_off) * 128;
#pragma unroll
            for (int t = 0; t < 8; t++) {
                int half = t >> 2;
                uint32_t coff = ((t & 3) * 16 + vcol8) * 2;
                uint32_t r[4];
                ldsm_x4_t(r, sb + AT_V + half * 8192 + SWZ(vrow + coff));
                mma16816h(oacc[2 * t],     pha, r[0], r[1]);
                mma16816h(oacc[2 * t + 1], pha, r[2], r[3]);
                mma16816h(oacc[2 * t],     pla, r[0], r[1]);
                mma16816h(oacc[2 * t + 1], pla, r[2], r[3]);
            }
        }
    }

    // ---- epilogue: normalize, write fp32 to g_ao ----
    float inv1 = 1.0f / l1s;
    float inv2 = 1.0f / l2s;
    int r1 = m0 + wq * 16 + (lane >> 2);
    int c0 = (lane & 3) * 2;
    float* dst1 = g_ao + ((size_t)(b * S_LEN + r1)) * HID + h * HD;
    float* dst2 = g_ao + ((size_t)(b * S_LEN + r1 + 8)) * HID + h * HD;
#pragma unroll
    for (int ng = 0; ng < 16; ng++) {
        int d = ng * 8 + c0;
        *(float2*)(dst1 + d) = make_float2(oacc[ng][0] * inv1, oacc[ng][1] * inv1);
        *(float2*)(dst2 + d) = make_float2(oacc[ng][2] * inv2, oacc[ng][3] * inv2);
    }
}

// ---------------------------------------------------------------------------
// Launch
// ---------------------------------------------------------------------------
extern "C" void kernel_launch(void* const* d_in, const int* in_sizes, int n_in,
                              void* d_out, int out_size)
{
    const float* x  = (const float*)d_in[0];
    const float* wq = (const float*)d_in[1];
    const float* wk = (const float*)d_in[2];
    const float* wv = (const float*)d_in[3];
    const float* wo = (const float*)d_in[4];
    const float* kw = (const float*)d_in[5];
    float* out = (float*)d_out;

    cudaFuncSetAttribute(attn_mma, cudaFuncAttributeMaxDynamicSharedMemorySize,
                         ATTN_SMEM);
    cudaFuncSetAttribute(gemm_qkv_mma, cudaFuncAttributeMaxDynamicSharedMemorySize,
                         GEMM_SMEM);
    cudaFuncSetAttribute(gemm_wo_mma, cudaFuncAttributeMaxDynamicSharedMemorySize,
                         GEMM_SMEM);

    void *xh, *xl, *wqs, *wks, *wvs, *wos, *ao, *aoh, *aol;
    cudaGetSymbolAddress(&xh, g_xh);   cudaGetSymbolAddress(&xl, g_xl);
    cudaGetSymbolAddress(&wqs, g_wqs); cudaGetSymbolAddress(&wks, g_wks);
    cudaGetSymbolAddress(&wvs, g_wvs); cudaGetSymbolAddress(&wos, g_wos);
    cudaGetSymbolAddress(&ao, g_ao);
    cudaGetSymbolAddress(&aoh, g_aoh); cudaGetSymbolAddress(&aol, g_aol);

    auto splith = [&](const float* src, void* hi, void* lo, size_t n) {
        int n4 = (int)(n / 4);
        split_f32h<<<(n4 + 255) / 256, 256>>>((const float4*)src,
                                              (uint2*)hi, (uint2*)lo, n4);
    };
    auto roundh = [&](const float* src, void* dst, size_t n) {
        int n4 = (int)(n / 4);
        round_f32h<<<(n4 + 255) / 256, 256>>>((const float4*)src, (uint2*)dst, n4);
    };

    // presplit activations; round weights to single fp16
    splith(x, xh, xl, (size_t)MROWS * HID);
    roundh(wq, wqs, (size_t)2048 * HID);
    roundh(wk, wks, (size_t)512 * HID);
    roundh(wv, wvs, (size_t)512 * HID);
    roundh(wo, wos, (size_t)2048 * HID);

    // QKV projection (fp16 2-product)
    gemm_qkv_mma<<<dim3(24, 32), 512, GEMM_SMEM>>>();

    // RoPE (fp32, in place)
    rope_q<<<BATCH * NH * S_LEN / 4, 256>>>();
    rope_k<<<BATCH * NKV * S_LEN / 4, 256>>>();

    // Attention (fp16 2-product)
    attn_mma<<<dim3(S_LEN / 128, NH, BATCH), 256, ATTN_SMEM>>>(kw);

    // presplit attention output for the WO GEMM
    splith((const float*)ao, aoh, aol, (size_t)MROWS * HID);

    // Output projection (fp16 2-product)
    gemm_wo_mma<<<dim3(16, 32), 512, GEMM_SMEM>>>(out);
}

// round 11
// speedup vs baseline: 1.7220x; 1.1334x over previous
#include <cuda_runtime.h>
#include <cuda_bf16.h>
#include <cuda_fp16.h>
#include <math.h>
#include <cstdint>

#define S_LEN 2048
#define HID   2048
#define NH    16
#define NKV   4
#define HD    128
#define BATCH 2
#define MROWS (BATCH * S_LEN)          // 4096

// ---------------- fp32 scratch ----------------
__device__ float g_q[(size_t)BATCH * NH  * S_LEN * HD];   // [b][h][s][d]
__device__ float g_k[(size_t)BATCH * NKV * S_LEN * HD];   // pre-rope
__device__ float g_v[(size_t)BATCH * NKV * S_LEN * HD];

// ---------------- fp16 scratch ----------------
__device__ __half g_k16[(size_t)BATCH * NKV * S_LEN * HD];  // post-rope, rounded
__device__ __half g_v16[(size_t)BATCH * NKV * S_LEN * HD];  // rounded
__device__ __half g_xh[(size_t)MROWS * HID],  g_xl[(size_t)MROWS * HID];
__device__ __half g_aoh[(size_t)MROWS * HID], g_aol[(size_t)MROWS * HID];
__device__ __half g_wqs[(size_t)2048 * HID];
__device__ __half g_wks[(size_t)512  * HID];
__device__ __half g_wvs[(size_t)512  * HID];
__device__ __half g_wos[(size_t)2048 * HID];

// ===========================================================================
// Helpers
// ===========================================================================
__device__ __forceinline__ uint32_t smem_u32(const void* p) {
    uint32_t a;
    asm("{ .reg .u64 t; cvta.to.shared.u64 t, %1; cvt.u32.u64 %0, t; }"
        : "=r"(a) : "l"(p));
    return a;
}
__device__ __forceinline__ void ldsm_x4(uint32_t r[4], uint32_t a) {
    asm volatile("ldmatrix.sync.aligned.m8n8.x4.shared.b16 {%0,%1,%2,%3}, [%4];"
                 : "=r"(r[0]), "=r"(r[1]), "=r"(r[2]), "=r"(r[3]) : "r"(a));
}
__device__ __forceinline__ void ldsm_x4_t(uint32_t r[4], uint32_t a) {
    asm volatile("ldmatrix.sync.aligned.m8n8.x4.trans.shared.b16 {%0,%1,%2,%3}, [%4];"
                 : "=r"(r[0]), "=r"(r[1]), "=r"(r[2]), "=r"(r[3]) : "r"(a));
}
__device__ __forceinline__ void mma16816h(float c[4], const uint32_t a[4],
                                          uint32_t b0, uint32_t b1) {
    asm volatile("mma.sync.aligned.m16n8k16.row.col.f32.f16.f16.f32 "
                 "{%0,%1,%2,%3}, {%4,%5,%6,%7}, {%8,%9}, {%0,%1,%2,%3};"
                 : "+f"(c[0]), "+f"(c[1]), "+f"(c[2]), "+f"(c[3])
                 : "r"(a[0]), "r"(a[1]), "r"(a[2]), "r"(a[3]), "r"(b0), "r"(b1));
}
__device__ __forceinline__ void split2h(float x0, float x1, uint32_t& hi, uint32_t& lo) {
    asm("cvt.rn.f16x2.f32 %0, %1, %2;" : "=r"(hi) : "f"(x1), "f"(x0));
    __half2 hv = *reinterpret_cast<__half2*>(&hi);
    float l0 = x0 - __half2float(__low2half(hv));
    float l1 = x1 - __half2float(__high2half(hv));
    asm("cvt.rn.f16x2.f32 %0, %1, %2;" : "=r"(lo) : "f"(l1), "f"(l0));
}
__device__ __forceinline__ uint32_t pack2h(float x0, float x1) {
    uint32_t r;
    asm("cvt.rn.f16x2.f32 %0, %1, %2;" : "=r"(r) : "f"(x1), "f"(x0));
    return r;
}
__device__ __forceinline__ void cp_async16(uint32_t dst, const void* src) {
    asm volatile("cp.async.cg.shared.global [%0], [%1], 16;" :: "r"(dst), "l"(src));
}
#define CP_COMMIT() asm volatile("cp.async.commit_group;" ::: "memory")
#define CP_WAIT(n)  asm volatile("cp.async.wait_group %0;" :: "n"(n) : "memory")

#define SWZ(o) ((o) ^ (((o) >> 3) & 0x70))

// ===========================================================================
// Conversion passes
// ===========================================================================
__global__ void split_f32h(const float4* __restrict__ src,
                           uint2* __restrict__ hi, uint2* __restrict__ lo, int n4)
{
    int i = blockIdx.x * blockDim.x + threadIdx.x;
    if (i < n4) {
        float4 v = src[i];
        uint32_t h0, l0, h1, l1;
        split2h(v.x, v.y, h0, l0);
        split2h(v.z, v.w, h1, l1);
        hi[i] = make_uint2(h0, h1);
        lo[i] = make_uint2(l0, l1);
    }
}
__global__ void round_f32h(const float4* __restrict__ src,
                           uint2* __restrict__ dst, int n4)
{
    int i = blockIdx.x * blockDim.x + threadIdx.x;
    if (i < n4) {
        float4 v = src[i];
        dst[i] = make_uint2(pack2h(v.x, v.y), pack2h(v.z, v.w));
    }
}

// ===========================================================================
// fp16 2-product GEMM (R9 verbatim — at HMMA roofline)
// ===========================================================================
#define KCHUNKS 64
#define GSTAGE  32768
#define GEMM_SMEM (2 * GSTAGE)

__device__ __forceinline__ void gemm_tile_512(
    const __half* __restrict__ Ah, const __half* __restrict__ Al,
    const __half* __restrict__ Bs,
    int m0, int n0, float cacc[8][4], char* smem)
{
    int tid = threadIdx.x;
    int warp = tid >> 5, lane = tid & 31;
    int wm = warp >> 1, wn = warp & 1;
    int lr16 = lane & 15, lhalf = (lane >> 4) * 16;
    uint32_t sbase = smem_u32(smem);

    int ar = tid >> 2;
    int aq = (tid & 3) * 32;
    int p0 = aq >> 6,        k0 = (aq & 63) >> 1;
    int p1 = (aq + 16) >> 6, k1 = ((aq + 16) & 63) >> 1;
    const __half* a0 = (p0 ? Al : Ah) + (size_t)(m0 + ar) * HID + k0;
    const __half* a1 = (p1 ? Al : Ah) + (size_t)(m0 + ar) * HID + k1;
    bool bact = aq < 64;
    const __half* b0s = Bs + (size_t)(n0 + ar) * HID + (aq >> 1);
    const __half* b1s = b0s + 8;
    uint32_t d0 = SWZ((uint32_t)ar * 128 + aq);
    uint32_t d1 = SWZ((uint32_t)ar * 128 + aq + 16);

#pragma unroll
    for (int ng = 0; ng < 8; ng++)
#pragma unroll
        for (int i = 0; i < 4; i++) cacc[ng][i] = 0.f;

    auto load_stage = [&](int s, int c) {
        uint32_t st = sbase + s * GSTAGE;
        cp_async16(st + d0, a0 + c * 32);
        cp_async16(st + d1, a1 + c * 32);
        if (bact) {
            cp_async16(st + 16384 + d0, b0s + c * 32);
            cp_async16(st + 16384 + d1, b1s + c * 32);
        }
        CP_COMMIT();
    };

    load_stage(0, 0);
    load_stage(1, 1);

    for (int c = 0; c < KCHUNKS; c++) {
        if (c + 1 < KCHUNKS) CP_WAIT(1); else CP_WAIT(0);
        __syncthreads();

        uint32_t abase = sbase + (c & 1) * GSTAGE;
        uint32_t bbase = abase + 16384;

#pragma unroll
        for (int seg = 0; seg < 2; seg++) {
            int sa = seg * 64;
#pragma unroll
            for (int kk = 0; kk < 2; kk++) {
                uint32_t af[4];
                ldsm_x4(af, abase + SWZ((uint32_t)(wm * 16 + lr16) * 128
                                        + sa + kk * 32 + lhalf));
                uint32_t b0[8], b1[8];
#pragma unroll
                for (int t = 0; t < 4; t++) {
                    uint32_t r[4];
                    ldsm_x4(r, bbase + SWZ((uint32_t)(wn * 64 + t * 16 + lr16) * 128
                                           + kk * 32 + lhalf));
                    b0[2 * t] = r[0]; b0[2 * t + 1] = r[1];
                    b1[2 * t] = r[2]; b1[2 * t + 1] = r[3];
                }
#pragma unroll
                for (int ng = 0; ng < 8; ng++)
                    mma16816h(cacc[ng], af, b0[ng], b1[ng]);
            }
        }
        __syncthreads();
        if (c + 2 < KCHUNKS) load_stage(c & 1, c + 2);
    }
}

__global__ void __launch_bounds__(512, 1) gemm_qkv_mma()
{
    extern __shared__ char smem[];
    int nt = blockIdx.x;
    int m0 = blockIdx.y * 128;

    const __half* Bs; float* dst_base; int h, nkvh;
    if (nt < 16)      { Bs = g_wqs; h = nt;      dst_base = g_q; nkvh = NH;  }
    else if (nt < 20) { Bs = g_wks; h = nt - 16; dst_base = g_k; nkvh = NKV; }
    else              { Bs = g_wvs; h = nt - 20; dst_base = g_v; nkvh = NKV; }

    float cacc[8][4];
    gemm_tile_512(g_xh, g_xl, Bs, m0, h * HD, cacc, smem);

    int tid = threadIdx.x;
    int warp = tid >> 5, lane = tid & 31;
    int wm = warp >> 1, wn = warp & 1;
    int r0 = lane >> 2, c0 = (lane & 3) * 2;

#pragma unroll
    for (int ng = 0; ng < 8; ng++) {
        int col = wn * 64 + ng * 8 + c0;
#pragma unroll
        for (int half = 0; half < 2; half++) {
            int mg = m0 + wm * 16 + r0 + half * 8;
            int b = mg >> 11, s = mg & (S_LEN - 1);
            float* d = dst_base + ((size_t)(b * nkvh + h) * S_LEN + s) * HD + col;
            *(float2*)d = make_float2(cacc[ng][2 * half], cacc[ng][2 * half + 1]);
        }
    }
}

__global__ void __launch_bounds__(512, 1) gemm_wo_mma(float* __restrict__ out)
{
    extern __shared__ char smem[];
    int n0 = blockIdx.x * 128;
    int m0 = blockIdx.y * 128;

    float cacc[8][4];
    gemm_tile_512(g_aoh, g_aol, g_wos, m0, n0, cacc, smem);

    int tid = threadIdx.x;
    int warp = tid >> 5, lane = tid & 31;
    int wm = warp >> 1, wn = warp & 1;
    int r0 = lane >> 2, c0 = (lane & 3) * 2;

#pragma unroll
    for (int ng = 0; ng < 8; ng++) {
        int col = n0 + wn * 64 + ng * 8 + c0;
#pragma unroll
        for (int half = 0; half < 2; half++) {
            int mg = m0 + wm * 16 + r0 + half * 8;
            *(float2*)&out[(size_t)mg * HID + col] =
                make_float2(cacc[ng][2 * half], cacc[ng][2 * half + 1]);
        }
    }
}

// ---------------------------------------------------------------------------
// RoPE. Q: fp32 in-place. K: fp32 in -> fp16 out (post-rope round).
// 256 threads = 4 rows per block.
// ---------------------------------------------------------------------------
__global__ void rope_q()
{
    int r = blockIdx.x * 4 + (threadIdx.x >> 6);
    int d = threadIdx.x & 63;
    float* base = g_q + (size_t)r * HD;
    int s = r & (S_LEN - 1);
    float inv = (float)exp2(-(double)d * 0.20762050593046747);
    float ang = (float)s * inv;
    float sn, cs;
    sincosf(ang, &sn, &cs);
    float x1 = base[d], x2 = base[d + 64];
    base[d]      = x1 * cs - x2 * sn;
    base[d + 64] = x1 * sn + x2 * cs;
}
__global__ void rope_k16()
{
    int r = blockIdx.x * 4 + (threadIdx.x >> 6);
    int d = threadIdx.x & 63;
    const float* base = g_k + (size_t)r * HD;
    int s = r & (S_LEN - 1);
    float inv = (float)exp2(-(double)d * 0.20762050593046747);
    float ang = (float)s * inv;
    float sn, cs;
    sincosf(ang, &sn, &cs);
    float x1 = base[d], x2 = base[d + 64];
    g_k16[(size_t)r * HD + d]      = __float2half_rn(x1 * cs - x2 * sn);
    g_k16[(size_t)r * HD + d + 64] = __float2half_rn(x1 * sn + x2 * cs);
}

// ===========================================================================
// HMMA flash attention, fp16 2-product, presplit fp16 K/V with 2-stage
// cp.async pipeline. BM=128 (8 warps x m16), BN=64, 256 threads.
// SMEM: QH 32K | QL 32K | stage0 [K 16K | V 16K] | stage1 [K 16K | V 16K]
// Each 16K tile: two 8K halves by d (d 0-63, 64-127), rows of 128B, SW128.
// ===========================================================================
#define AT_QH 0
#define AT_QL 32768
#define AT_KV 65536
#define KVSTAGE 32768
#define ATTN_SMEM 131072

__global__ void __launch_bounds__(256, 1) attn_mma(const float* __restrict__ kw)
{
    extern __shared__ char smem[];
    uint32_t sb = smem_u32(smem);

    int tid = threadIdx.x;
    int wq = tid >> 5, lane = tid & 31;
    int lr16 = lane & 15;
    int lhalf = (lane >> 4) * 16;

    int mt = blockIdx.x, h = blockIdx.y, b = blockIdx.z;
    int m0 = mt * 128;
    int kh = h >> 2;
    float scale = kw[h] * 0.08838834764831845f;

    const float* qg = g_q + ((size_t)(b * NH + h) * S_LEN + m0) * HD;
    size_t kvrow0 = (size_t)(b * NKV + kh) * S_LEN;

    // ---- KV cp.async mapping (fp16, 64B/thread/tile each for K and V) ----
    int krow = tid >> 2;               // 0..63
    int kd = (tid & 3) * 32;           // d base
    const __half* kbase_g = g_k16 + (kvrow0 + krow) * HD + kd;
    const __half* vbase_g = g_v16 + (kvrow0 + krow) * HD + kd;
    uint32_t kvoff[4];
#pragma unroll
    for (int j = 0; j < 4; j++) {
        int d = kd + j * 8;
        kvoff[j] = (uint32_t)(d >> 6) * 8192 + SWZ((uint32_t)krow * 128 + (d & 63) * 2);
    }
    auto load_kv = [&](int s, int nt) {
        uint32_t st = sb + AT_KV + s * KVSTAGE;
        const __half* kp = kbase_g + (size_t)nt * 64 * HD;
        const __half* vp = vbase_g + (size_t)nt * 64 * HD;
#pragma unroll
        for (int j = 0; j < 4; j++) {
            cp_async16(st + kvoff[j], kp + j * 8);
            cp_async16(st + 16384 + kvoff[j], vp + j * 8);
        }
        CP_COMMIT();
    };

    int ntiles = 2 * mt + 2;
    load_kv(0, 0);
    load_kv(1, 1);

    // ---- load + convert + scale Q (fp16 hi/lo) ----
    {
        int row = tid >> 1;
        int dst = (tid & 1) * 64;
        const float* src = qg + (size_t)row * HD + dst;
        char* qh = smem + AT_QH + (dst >> 6) * 16384;
        char* ql = smem + AT_QL + (dst >> 6) * 16384;
#pragma unroll
        for (int j = 0; j < 16; j++) {
            float4 v = *(const float4*)(src + j * 4);
            v.x *= scale; v.y *= scale; v.z *= scale; v.w *= scale;
            uint32_t h0, l0, h1, l1;
            split2h(v.x, v.y, h0, l0);
            split2h(v.z, v.w, h1, l1);
            uint32_t off = (uint32_t)row * 128 + ((dst + j * 4) & 63) * 2;
            *(uint2*)(qh + SWZ(off)) = make_uint2(h0, h1);
            *(uint2*)(ql + SWZ(off)) = make_uint2(l0, l1);
        }
    }

    float m1 = -1e30f, m2 = -1e30f, l1s = 0.f, l2s = 0.f;
    float oacc[16][4];
#pragma unroll
    for (int ng = 0; ng < 16; ng++)
#pragma unroll
        for (int i = 0; i < 4; i++) oacc[ng][i] = 0.f;

    int vrow_off = (lane & 7) + ((lane >> 3) & 1) * 8;
    int vcol8 = (lane >> 4) * 8;

    for (int nt = 0; nt < ntiles; nt++) {
        int n0 = nt * 64;
        if (nt + 1 < ntiles) CP_WAIT(1); else CP_WAIT(0);
        __syncthreads();

        uint32_t kstage = sb + AT_KV + (nt & 1) * KVSTAGE;
        uint32_t vstage = kstage + 16384;

        // ---- S = Q K^T (Qh*K + Ql*K) ----
        float sacc[8][4];
#pragma unroll
        for (int ng = 0; ng < 8; ng++)
#pragma unroll
            for (int i = 0; i < 4; i++) sacc[ng][i] = 0.f;

#pragma unroll
        for (int seg = 0; seg < 2; seg++) {
            uint32_t qbase = sb + ((seg == 1) ? AT_QL : AT_QH);
#pragma unroll
            for (int ks = 0; ks < 8; ks++) {
                int half = ks >> 2;
                uint32_t koff = (ks & 3) * 32 + lhalf;
                uint32_t af[4];
                ldsm_x4(af, qbase + half * 16384
                            + SWZ((uint32_t)(wq * 16 + lr16) * 128 + koff));
                uint32_t b0[8], b1[8];
#pragma unroll
                for (int t = 0; t < 4; t++) {
                    uint32_t r[4];
                    ldsm_x4(r, kstage + half * 8192
                               + SWZ((uint32_t)(t * 16 + lr16) * 128 + koff));
                    b0[2 * t] = r[0]; b0[2 * t + 1] = r[1];
                    b1[2 * t] = r[2]; b1[2 * t + 1] = r[3];
                }
#pragma unroll
                for (int ng = 0; ng < 8; ng++)
                    mma16816h(sacc[ng], af, b0[ng], b1[ng]);
            }
        }

        // ---- causal mask (last two tiles only) ----
        if (nt >= 2 * mt) {
            int rg1 = m0 + wq * 16 + (lane >> 2);
            int rg2 = rg1 + 8;
            int cb = n0 + (lane & 3) * 2;
#pragma unroll
            for (int ng = 0; ng < 8; ng++) {
                int c0g = cb + ng * 8;
                if (c0g > rg1)     sacc[ng][0] = -1e30f;
                if (c0g + 1 > rg1) sacc[ng][1] = -1e30f;
                if (c0g > rg2)     sacc[ng][2] = -1e30f;
                if (c0g + 1 > rg2) sacc[ng][3] = -1e30f;
            }
        }

        // ---- online softmax ----
        float rmax1 = -1e30f, rmax2 = -1e30f;
#pragma unroll
        for (int ng = 0; ng < 8; ng++) {
            rmax1 = fmaxf(rmax1, fmaxf(sacc[ng][0], sacc[ng][1]));
            rmax2 = fmaxf(rmax2, fmaxf(sacc[ng][2], sacc[ng][3]));
        }
        rmax1 = fmaxf(rmax1, __shfl_xor_sync(0xffffffffu, rmax1, 1));
        rmax1 = fmaxf(rmax1, __shfl_xor_sync(0xffffffffu, rmax1, 2));
        rmax2 = fmaxf(rmax2, __shfl_xor_sync(0xffffffffu, rmax2, 1));
        rmax2 = fmaxf(rmax2, __shfl_xor_sync(0xffffffffu, rmax2, 2));

        float mn1 = fmaxf(m1, rmax1);
        float mn2 = fmaxf(m2, rmax2);
        float alpha1 = __expf(m1 - mn1);
        float alpha2 = __expf(m2 - mn2);
        m1 = mn1; m2 = mn2;

        float rsum1 = 0.f, rsum2 = 0.f;
#pragma unroll
        for (int ng = 0; ng < 8; ng++) {
            sacc[ng][0] = __expf(sacc[ng][0] - mn1);
            sacc[ng][1] = __expf(sacc[ng][1] - mn1);
            sacc[ng][2] = __expf(sacc[ng][2] - mn2);
            sacc[ng][3] = __expf(sacc[ng][3] - mn2);
            rsum1 += sacc[ng][0] + sacc[ng][1];
            rsum2 += sacc[ng][2] + sacc[ng][3];
        }
        rsum1 += __shfl_xor_sync(0xffffffffu, rsum1, 1);
        rsum1 += __shfl_xor_sync(0xffffffffu, rsum1, 2);
        rsum2 += __shfl_xor_sync(0xffffffffu, rsum2, 1);
        rsum2 += __shfl_xor_sync(0xffffffffu, rsum2, 2);
        l1s = l1s * alpha1 + rsum1;
        l2s = l2s * alpha2 + rsum2;

#pragma unroll
        for (int ng = 0; ng < 16; ng++) {
            oacc[ng][0] *= alpha1; oacc[ng][1] *= alpha1;
            oacc[ng][2] *= alpha2; oacc[ng][3] *= alpha2;
        }

        // ---- O += P V (Ph*V + Pl*V), P split in registers ----
#pragma unroll
        for (int ks = 0; ks < 4; ks++) {
            uint32_t pha[4], pla[4];
            split2h(sacc[2 * ks][0],     sacc[2 * ks][1],     pha[0], pla[0]);
            split2h(sacc[2 * ks][2],     sacc[2 * ks][3],     pha[1], pla[1]);
            split2h(sacc[2 * ks + 1][0], sacc[2 * ks + 1][1], pha[2], pla[2]);
            split2h(sacc[2 * ks + 1][2], sacc[2 * ks + 1][3], pha[3], pla[3]);

            uint32_t vrow = (uint32_t)(ks * 16 + vrow_off) * 128;
#pragma unroll
            for (int t = 0; t < 8; t++) {
                int half = t >> 2;
                uint32_t coff = ((t & 3) * 16 + vcol8) * 2;
                uint32_t r[4];
                ldsm_x4_t(r, vstage + half * 8192 + SWZ(vrow + coff));
                mma16816h(oacc[2 * t],     pha, r[0], r[1]);
                mma16816h(oacc[2 * t + 1], pha, r[2], r[3]);
                mma16816h(oacc[2 * t],     pla, r[0], r[1]);
                mma16816h(oacc[2 * t + 1], pla, r[2], r[3]);
            }
        }

        __syncthreads();
        if (nt + 2 < ntiles) load_kv(nt & 1, nt + 2);
    }

    // ---- epilogue: normalize, split fp16 hi/lo directly to g_aoh/g_aol ----
    float inv1 = 1.0f / l1s;
    float inv2 = 1.0f / l2s;
    int r1 = m0 + wq * 16 + (lane >> 2);
    int c0 = (lane & 3) * 2;
    size_t base1 = ((size_t)(b * S_LEN + r1)) * HID + h * HD;
    size_t base2 = ((size_t)(b * S_LEN + r1 + 8)) * HID + h * HD;
#pragma unroll
    for (int ng = 0; ng < 16; ng++) {
        int d = ng * 8 + c0;
        uint32_t hA, lA;
        split2h(oacc[ng][0] * inv1, oacc[ng][1] * inv1, hA, lA);
        *(uint32_t*)&g_aoh[base1 + d] = hA;
        *(uint32_t*)&g_aol[base1 + d] = lA;
        split2h(oacc[ng][2] * inv2, oacc[ng][3] * inv2, hA, lA);
        *(uint32_t*)&g_aoh[base2 + d] = hA;
        *(uint32_t*)&g_aol[base2 + d] = lA;
    }
}

// ---------------------------------------------------------------------------
// Launch
// ---------------------------------------------------------------------------
extern "C" void kernel_launch(void* const* d_in, const int* in_sizes, int n_in,
                              void* d_out, int out_size)
{
    const float* x  = (const float*)d_in[0];
    const float* wq = (const float*)d_in[1];
    const float* wk = (const float*)d_in[2];
    const float* wv = (const float*)d_in[3];
    const float* wo = (const float*)d_in[4];
    const float* kw = (const float*)d_in[5];
    float* out = (float*)d_out;

    cudaFuncSetAttribute(attn_mma, cudaFuncAttributeMaxDynamicSharedMemorySize,
                         ATTN_SMEM);
    cudaFuncSetAttribute(gemm_qkv_mma, cudaFuncAttributeMaxDynamicSharedMemorySize,
                         GEMM_SMEM);
    cudaFuncSetAttribute(gemm_wo_mma, cudaFuncAttributeMaxDynamicSharedMemorySize,
                         GEMM_SMEM);

    void *xh, *xl, *wqs, *wks, *wvs, *wos, *vf, *v16;
    cudaGetSymbolAddress(&xh, g_xh);   cudaGetSymbolAddress(&xl, g_xl);
    cudaGetSymbolAddress(&wqs, g_wqs); cudaGetSymbolAddress(&wks, g_wks);
    cudaGetSymbolAddress(&wvs, g_wvs); cudaGetSymbolAddress(&wos, g_wos);
    cudaGetSymbolAddress(&vf, g_v);    cudaGetSymbolAddress(&v16, g_v16);

    auto splith = [&](const float* src, void* hi, void* lo, size_t n) {
        int n4 = (int)(n / 4);
        split_f32h<<<(n4 + 255) / 256, 256>>>((const float4*)src,
                                              (uint2*)hi, (uint2*)lo, n4);
    };
    auto roundh = [&](const float* src, void* dst, size_t n) {
        int n4 = (int)(n / 4);
        round_f32h<<<(n4 + 255) / 256, 256>>>((const float4*)src, (uint2*)dst, n4);
    };

    // presplit activations; round weights to single fp16
    splith(x, xh, xl, (size_t)MROWS * HID);
    roundh(wq, wqs, (size_t)2048 * HID);
    roundh(wk, wks, (size_t)512 * HID);
    roundh(wv, wvs, (size_t)512 * HID);
    roundh(wo, wos, (size_t)2048 * HID);

    // QKV projection (fp16 2-product)
    gemm_qkv_mma<<<dim3(24, 32), 512, GEMM_SMEM>>>();

    // RoPE: Q fp32 in-place; K fused rope+round -> fp16. V round -> fp16.
    rope_q<<<BATCH * NH * S_LEN / 4, 256>>>();
    rope_k16<<<BATCH * NKV * S_LEN / 4, 256>>>();
    roundh((const float*)vf, v16, (size_t)BATCH * NKV * S_LEN * HD);

    // Attention (fp16 2-product, cp.async KV pipeline; writes g_aoh/g_aol)
    attn_mma<<<dim3(S_LEN / 128, NH, BATCH), 256, ATTN_SMEM>>>(kw);

    // Output projection (fp16 2-product)
    gemm_wo_mma<<<dim3(16, 32), 512, GEMM_SMEM>>>(out);
}